// round 1
// baseline (speedup 1.0000x reference)
#include <cuda_runtime.h>
#include <math.h>

#define D_MODEL 1024
#define NHEADS 16
#define HD 64
#define BATCH 2
#define SEQ 2048
#define NTOK (BATCH * SEQ)   // 4096

// Scratch (no allocations allowed)
__device__ float g_q[(size_t)NTOK * D_MODEL];    // [B,H,S,hd]
__device__ float g_k[(size_t)NTOK * D_MODEL];    // [B,H,S,hd]
__device__ float g_v[(size_t)NTOK * D_MODEL];    // [B,H,S,hd]
__device__ float g_ctx[(size_t)NTOK * D_MODEL];  // [B,S,D] flat

// ---------------------------------------------------------------------------
// GEMM: C[M=4096, N=1024] = A[4096,1024] @ W[1024,1024] + bias
// 128x128 block tile, BK=8, 256 threads, 8x8 register microtile.
// split=1: write into [B,H,S,hd] head-split layout; split=0: flat [M,N].
// ---------------------------------------------------------------------------
__global__ __launch_bounds__(256) void gemm_bias_kernel(
    const float* __restrict__ A, const float* __restrict__ W,
    const float* __restrict__ bias, float* __restrict__ C, int split)
{
    __shared__ float As[8][128];   // [k][m]
    __shared__ float Ws[8][128];   // [k][n]

    const int tid = threadIdx.x;
    const int bm = blockIdx.y * 128;
    const int bn = blockIdx.x * 128;
    const int ty = tid >> 4;       // 0..15
    const int tx = tid & 15;       // 0..15

    float acc[8][8];
    #pragma unroll
    for (int i = 0; i < 8; i++)
        #pragma unroll
        for (int j = 0; j < 8; j++) acc[i][j] = 0.0f;

    const int arow = tid >> 1;               // 0..127
    const int acol = (tid & 1) * 4;          // 0 or 4
    const int wrow = tid >> 5;               // 0..7
    const int wcol = (tid & 31) * 4;         // 0..124

    const float* Aptr = A + (size_t)(bm + arow) * D_MODEL + acol;
    const float* Wptr = W + (size_t)wrow * D_MODEL + bn + wcol;

    for (int k0 = 0; k0 < D_MODEL; k0 += 8) {
        float4 av = *(const float4*)(Aptr + k0);
        float4 wv = *(const float4*)(Wptr + (size_t)k0 * D_MODEL);
        __syncthreads();
        As[acol + 0][arow] = av.x;
        As[acol + 1][arow] = av.y;
        As[acol + 2][arow] = av.z;
        As[acol + 3][arow] = av.w;
        *(float4*)&Ws[wrow][wcol] = wv;
        __syncthreads();
        #pragma unroll
        for (int k = 0; k < 8; k++) {
            float4 a0 = *(const float4*)&As[k][ty * 8];
            float4 a1 = *(const float4*)&As[k][ty * 8 + 4];
            float4 b0 = *(const float4*)&Ws[k][tx * 8];
            float4 b1 = *(const float4*)&Ws[k][tx * 8 + 4];
            float a[8] = {a0.x, a0.y, a0.z, a0.w, a1.x, a1.y, a1.z, a1.w};
            float b[8] = {b0.x, b0.y, b0.z, b0.w, b1.x, b1.y, b1.z, b1.w};
            #pragma unroll
            for (int i = 0; i < 8; i++)
                #pragma unroll
                for (int j = 0; j < 8; j++)
                    acc[i][j] += a[i] * b[j];
        }
    }

    #pragma unroll
    for (int i = 0; i < 8; i++) {
        const int m = bm + ty * 8 + i;
        const int bb = m >> 11;        // token batch
        const int ss = m & 2047;       // token seq pos
        #pragma unroll
        for (int jv = 0; jv < 8; jv += 4) {
            const int n0 = bn + tx * 8 + jv;
            float4 bv = *(const float4*)(bias + n0);
            float4 r;
            r.x = acc[i][jv + 0] + bv.x;
            r.y = acc[i][jv + 1] + bv.y;
            r.z = acc[i][jv + 2] + bv.z;
            r.w = acc[i][jv + 3] + bv.w;
            if (split) {
                const int hh = n0 >> 6;
                const int dd = n0 & 63;
                *(float4*)(C + (((size_t)(bb * NHEADS + hh) * SEQ + ss) * HD + dd)) = r;
            } else {
                *(float4*)(C + (size_t)m * D_MODEL + n0) = r;
            }
        }
    }
}

// ---------------------------------------------------------------------------
// Flash attention, fp32. One CTA per (q-tile=64, head, batch). BKV=64.
// 256 threads; 16x16 thread grid; each thread owns 4 rows x 4 cols of the
// 64x64 score tile and the 64x64 output tile.
// ---------------------------------------------------------------------------
#define PADT 68

__global__ __launch_bounds__(256) void attn_kernel(
    const float* __restrict__ Qa, const float* __restrict__ Ka,
    const float* __restrict__ Va, float* __restrict__ ctx)
{
    extern __shared__ float sm[];
    float* QsT = sm;                  // [hd=64][PADT rows]  (transposed)
    float* KsT = sm + 64 * PADT;      // [hd=64][PADT rows]  (transposed)
    float* Vs  = sm + 2 * 64 * PADT;  // [kvrow=64][PADT cols] row-major
    float* Ps  = sm + 3 * 64 * PADT;  // [qrow=64][PADT cols] row-major

    const int qt = blockIdx.x;
    const int h  = blockIdx.y;
    const int b  = blockIdx.z;
    const int bh = b * NHEADS + h;
    const float* Qg = Qa + (size_t)bh * SEQ * HD;
    const float* Kg = Ka + (size_t)bh * SEQ * HD;
    const float* Vg = Va + (size_t)bh * SEQ * HD;

    const int tid = threadIdx.x;
    const int ty = tid >> 4;   // 0..15
    const int tx = tid & 15;   // 0..15
    const int q0 = qt * 64;
    const float scale = 0.125f;   // 1/sqrt(64)

    // Load Q tile, transposed + pre-scaled
    #pragma unroll
    for (int l = 0; l < 4; l++) {
        int idx = tid + l * 256;
        int r = idx >> 4;
        int c = (idx & 15) * 4;
        float4 qv = *(const float4*)(Qg + (size_t)(q0 + r) * HD + c);
        QsT[(c + 0) * PADT + r] = qv.x * scale;
        QsT[(c + 1) * PADT + r] = qv.y * scale;
        QsT[(c + 2) * PADT + r] = qv.z * scale;
        QsT[(c + 3) * PADT + r] = qv.w * scale;
    }

    float m_i[4], l_i[4], o[4][4];
    #pragma unroll
    for (int i = 0; i < 4; i++) {
        m_i[i] = -1e30f;
        l_i[i] = 0.0f;
        #pragma unroll
        for (int j = 0; j < 4; j++) o[i][j] = 0.0f;
    }

    for (int j0 = 0; j0 <= q0; j0 += 64) {
        __syncthreads();  // protect K/V/P from prior iteration readers
        #pragma unroll
        for (int l = 0; l < 4; l++) {
            int idx = tid + l * 256;
            int r = idx >> 4;
            int c = (idx & 15) * 4;
            float4 kv = *(const float4*)(Kg + (size_t)(j0 + r) * HD + c);
            KsT[(c + 0) * PADT + r] = kv.x;
            KsT[(c + 1) * PADT + r] = kv.y;
            KsT[(c + 2) * PADT + r] = kv.z;
            KsT[(c + 3) * PADT + r] = kv.w;
            float4 vv = *(const float4*)(Vg + (size_t)(j0 + r) * HD + c);
            *(float4*)(Vs + r * PADT + c) = vv;
        }
        __syncthreads();

        // S = Q @ K^T  (64x64x64)
        float sc[4][4];
        #pragma unroll
        for (int i = 0; i < 4; i++)
            #pragma unroll
            for (int j = 0; j < 4; j++) sc[i][j] = 0.0f;

        #pragma unroll 4
        for (int k = 0; k < HD; k++) {
            float4 a = *(const float4*)(QsT + k * PADT + ty * 4);
            float4 bv = *(const float4*)(KsT + k * PADT + tx * 4);
            float av[4] = {a.x, a.y, a.z, a.w};
            float bb[4] = {bv.x, bv.y, bv.z, bv.w};
            #pragma unroll
            for (int i = 0; i < 4; i++)
                #pragma unroll
                for (int j = 0; j < 4; j++)
                    sc[i][j] += av[i] * bb[j];
        }

        // Causal mask (diagonal tile only)
        if (j0 == q0) {
            #pragma unroll
            for (int i = 0; i < 4; i++)
                #pragma unroll
                for (int j = 0; j < 4; j++)
                    if (tx * 4 + j > ty * 4 + i) sc[i][j] = -1e30f;
        }

        // Online softmax update (row groups of 16 lanes)
        #pragma unroll
        for (int i = 0; i < 4; i++) {
            float mx = fmaxf(fmaxf(sc[i][0], sc[i][1]), fmaxf(sc[i][2], sc[i][3]));
            #pragma unroll
            for (int off = 8; off > 0; off >>= 1)
                mx = fmaxf(mx, __shfl_xor_sync(0xffffffffu, mx, off));
            float mnew = fmaxf(m_i[i], mx);
            float corr = __expf(m_i[i] - mnew);
            float p0 = __expf(sc[i][0] - mnew);
            float p1 = __expf(sc[i][1] - mnew);
            float p2 = __expf(sc[i][2] - mnew);
            float p3 = __expf(sc[i][3] - mnew);
            float rs = p0 + p1 + p2 + p3;
            #pragma unroll
            for (int off = 8; off > 0; off >>= 1)
                rs += __shfl_xor_sync(0xffffffffu, rs, off);
            l_i[i] = l_i[i] * corr + rs;
            m_i[i] = mnew;
            #pragma unroll
            for (int j = 0; j < 4; j++) o[i][j] *= corr;
            float4 pv = make_float4(p0, p1, p2, p3);
            *(float4*)(Ps + (ty * 4 + i) * PADT + tx * 4) = pv;
        }
        __syncthreads();

        // O += P @ V  (64x64x64)
        #pragma unroll 4
        for (int k = 0; k < 64; k++) {
            float4 vv = *(const float4*)(Vs + k * PADT + tx * 4);
            float p0 = Ps[(ty * 4 + 0) * PADT + k];
            float p1 = Ps[(ty * 4 + 1) * PADT + k];
            float p2 = Ps[(ty * 4 + 2) * PADT + k];
            float p3 = Ps[(ty * 4 + 3) * PADT + k];
            o[0][0] += p0 * vv.x; o[0][1] += p0 * vv.y; o[0][2] += p0 * vv.z; o[0][3] += p0 * vv.w;
            o[1][0] += p1 * vv.x; o[1][1] += p1 * vv.y; o[1][2] += p1 * vv.z; o[1][3] += p1 * vv.w;
            o[2][0] += p2 * vv.x; o[2][1] += p2 * vv.y; o[2][2] += p2 * vv.z; o[2][3] += p2 * vv.w;
            o[3][0] += p3 * vv.x; o[3][1] += p3 * vv.y; o[3][2] += p3 * vv.z; o[3][3] += p3 * vv.w;
        }
    }

    // Epilogue: normalize + write ctx flat [B,S,D]
    #pragma unroll
    for (int i = 0; i < 4; i++) {
        float inv = 1.0f / l_i[i];
        int tok = b * SEQ + q0 + ty * 4 + i;
        float4 ov;
        ov.x = o[i][0] * inv;
        ov.y = o[i][1] * inv;
        ov.z = o[i][2] * inv;
        ov.w = o[i][3] * inv;
        *(float4*)(ctx + (size_t)tok * D_MODEL + h * HD + tx * 4) = ov;
    }
}

// ---------------------------------------------------------------------------
extern "C" void kernel_launch(void* const* d_in, const int* in_sizes, int n_in,
                              void* d_out, int out_size)
{
    const float* x  = (const float*)d_in[0];
    const float* Wq = (const float*)d_in[1];
    const float* bq = (const float*)d_in[2];
    const float* Wk = (const float*)d_in[3];
    const float* bk = (const float*)d_in[4];
    const float* Wv = (const float*)d_in[5];
    const float* bv = (const float*)d_in[6];
    const float* Wo = (const float*)d_in[7];
    const float* bo = (const float*)d_in[8];
    float* out = (float*)d_out;

    float *qp, *kp, *vp, *cp;
    cudaGetSymbolAddress((void**)&qp, g_q);
    cudaGetSymbolAddress((void**)&kp, g_k);
    cudaGetSymbolAddress((void**)&vp, g_v);
    cudaGetSymbolAddress((void**)&cp, g_ctx);

    dim3 gg(D_MODEL / 128, NTOK / 128);   // (8, 32)
    gemm_bias_kernel<<<gg, 256>>>(x, Wq, bq, qp, 1);
    gemm_bias_kernel<<<gg, 256>>>(x, Wk, bk, kp, 1);
    gemm_bias_kernel<<<gg, 256>>>(x, Wv, bv, vp, 1);

    int smem = 4 * 64 * PADT * sizeof(float);  // 69632 bytes
    cudaFuncSetAttribute(attn_kernel, cudaFuncAttributeMaxDynamicSharedMemorySize, smem);
    dim3 ga(SEQ / 64, NHEADS, BATCH);          // (32, 16, 2)
    attn_kernel<<<ga, 256, smem>>>(qp, kp, vp, cp);

    gemm_bias_kernel<<<gg, 256>>>(cp, Wo, bo, out, 0);
}

// round 3
// speedup vs baseline: 1.5204x; 1.5204x over previous
#include <cuda_runtime.h>
#include <cuda_bf16.h>
#include <cstdint>
#include <math.h>

#define D_MODEL 1024
#define NHEADS 16
#define HD 64
#define BATCH 2
#define SEQ 2048
#define NTOK (BATCH * SEQ)   // 4096

// ---------------------------------------------------------------------------
// Scratch (no allocations allowed)
// ---------------------------------------------------------------------------
__device__ float g_q[(size_t)NTOK * D_MODEL];     // [B,H,S,hd]
__device__ float g_k[(size_t)NTOK * D_MODEL];
__device__ float g_v[(size_t)NTOK * D_MODEL];
__device__ float g_ctx[(size_t)NTOK * D_MODEL];   // [B,S,D]
__device__ __nv_bfloat16 g_xh[(size_t)NTOK * D_MODEL];
__device__ __nv_bfloat16 g_xl[(size_t)NTOK * D_MODEL];
__device__ __nv_bfloat16 g_cth[(size_t)NTOK * D_MODEL];
__device__ __nv_bfloat16 g_ctl[(size_t)NTOK * D_MODEL];
__device__ __nv_bfloat16 g_wh[(size_t)4 * D_MODEL * D_MODEL];  // transposed [n][k]
__device__ __nv_bfloat16 g_wl[(size_t)4 * D_MODEL * D_MODEL];

// ---------------------------------------------------------------------------
// Helpers (generic sm_80+ PTX only — NO tcgen05, harness targets plain sm_103)
// ---------------------------------------------------------------------------
__device__ __forceinline__ uint32_t smem_u32(const void* p) {
    uint32_t a;
    asm("{ .reg .u64 t; cvta.to.shared.u64 t, %1; cvt.u32.u64 %0, t; }" : "=r"(a) : "l"(p));
    return a;
}
__device__ __forceinline__ void cpa16(uint32_t s, const void* g) {
    asm volatile("cp.async.cg.shared.global [%0], [%1], 16;" :: "r"(s), "l"(g));
}
#define CP_COMMIT() asm volatile("cp.async.commit_group;" ::: "memory")
#define CP_WAIT1()  asm volatile("cp.async.wait_group 1;" ::: "memory")
#define CP_WAIT0()  asm volatile("cp.async.wait_group 0;" ::: "memory")

#define LDMX4(r, a) \
    asm volatile("ldmatrix.sync.aligned.m8n8.x4.shared.b16 {%0,%1,%2,%3}, [%4];" \
        : "=r"((r)[0]), "=r"((r)[1]), "=r"((r)[2]), "=r"((r)[3]) : "r"(a))

__device__ __forceinline__ void mma16816(float* c, const uint32_t* a, uint32_t b0, uint32_t b1) {
    asm volatile(
        "mma.sync.aligned.m16n8k16.row.col.f32.bf16.bf16.f32 "
        "{%0,%1,%2,%3}, {%4,%5,%6,%7}, {%8,%9}, {%0,%1,%2,%3};"
        : "+f"(c[0]), "+f"(c[1]), "+f"(c[2]), "+f"(c[3])
        : "r"(a[0]), "r"(a[1]), "r"(a[2]), "r"(a[3]), "r"(b0), "r"(b1));
}

// ---------------------------------------------------------------------------
// Conversion kernels
// ---------------------------------------------------------------------------
__global__ void split_kernel(const float* __restrict__ s, __nv_bfloat16* __restrict__ h,
                             __nv_bfloat16* __restrict__ l, int n) {
    int i = blockIdx.x * blockDim.x + threadIdx.x;
    int stride = gridDim.x * blockDim.x;
    for (; i < n; i += stride) {
        float v = s[i];
        __nv_bfloat16 hi = __float2bfloat16(v);
        h[i] = hi;
        l[i] = __float2bfloat16(v - __bfloat162float(hi));
    }
}

// W [k][n] fp32 -> hi/lo [n][k] bf16
__global__ void tsplit_kernel(const float* __restrict__ W, __nv_bfloat16* __restrict__ th,
                              __nv_bfloat16* __restrict__ tl) {
    __shared__ float t[32][33];
    int n0 = blockIdx.x * 32, k0 = blockIdx.y * 32;
    int x = threadIdx.x, y = threadIdx.y;  // 32x8
    #pragma unroll
    for (int j = 0; j < 32; j += 8)
        t[y + j][x] = W[(size_t)(k0 + y + j) * D_MODEL + n0 + x];
    __syncthreads();
    #pragma unroll
    for (int j = 0; j < 32; j += 8) {
        float v = t[x][y + j];
        __nv_bfloat16 hi = __float2bfloat16(v);
        size_t o = (size_t)(n0 + y + j) * D_MODEL + k0 + x;
        th[o] = hi;
        tl[o] = __float2bfloat16(v - __bfloat162float(hi));
    }
}

// ---------------------------------------------------------------------------
// mma.sync GEMM: C[4096,1024] = A @ B^T (+bias)
// A hi/lo [m][k], B hi/lo [n][k]. 128x128 tile, BK=32, split-bf16 (3 mma/tile).
// smem row stride 40 elems (80B) -> conflict-free ldmatrix.
// ---------------------------------------------------------------------------
#define ABYTES 10240u                 // one array tile: 128 rows * 40 elems * 2B
#define STAGEB (4u * ABYTES)          // Ah, Al, Bh, Bl
#define SMEM_GEMM (2u * STAGEB)       // 81920 B

__device__ __forceinline__ void issue_stage(
    uint32_t su, int stage, int k0, int tid, int bm, int bn,
    const __nv_bfloat16* __restrict__ Ah, const __nv_bfloat16* __restrict__ Al,
    const __nv_bfloat16* __restrict__ Bh, const __nv_bfloat16* __restrict__ Bl)
{
    uint32_t sb = su + (uint32_t)stage * STAGEB;
    #pragma unroll
    for (int j = 0; j < 2; j++) {
        int idx = tid + j * 256;
        int r = idx >> 2, c8 = idx & 3;
        uint32_t so = (uint32_t)(r * 40 + c8 * 8) * 2;
        size_t goA = (size_t)(bm + r) * D_MODEL + k0 + c8 * 8;
        size_t goB = (size_t)(bn + r) * D_MODEL + k0 + c8 * 8;
        cpa16(sb + 0u * ABYTES + so, Ah + goA);
        cpa16(sb + 1u * ABYTES + so, Al + goA);
        cpa16(sb + 2u * ABYTES + so, Bh + goB);
        cpa16(sb + 3u * ABYTES + so, Bl + goB);
    }
    CP_COMMIT();
}

__device__ __forceinline__ void st_out(float* __restrict__ C, int split, int m, int n, float2 v) {
    if (split) {
        int bb = m >> 11, ss = m & 2047, hh = n >> 6, dd = n & 63;
        *(float2*)(C + (((size_t)(bb * NHEADS + hh) * SEQ + ss) * HD + dd)) = v;
    } else {
        *(float2*)(C + (size_t)m * D_MODEL + n) = v;
    }
}

__global__ __launch_bounds__(256) void gemm_mma(
    const __nv_bfloat16* __restrict__ Ah, const __nv_bfloat16* __restrict__ Al,
    const __nv_bfloat16* __restrict__ Bh, const __nv_bfloat16* __restrict__ Bl,
    const float* __restrict__ bias, float* __restrict__ C, int split)
{
    extern __shared__ char smraw[];
    const uint32_t su = smem_u32(smraw);
    const int tid = threadIdx.x, lane = tid & 31, wid = tid >> 5;
    const int bm = blockIdx.y * 128, bn = blockIdx.x * 128;
    const int wm = (wid >> 2) * 64, wn = (wid & 3) * 32;

    float acc[4][4][4];
    #pragma unroll
    for (int i = 0; i < 4; i++)
        #pragma unroll
        for (int j = 0; j < 4; j++)
            #pragma unroll
            for (int q = 0; q < 4; q++) acc[i][j][q] = 0.0f;

    issue_stage(su, 0, 0, tid, bm, bn, Ah, Al, Bh, Bl);

    const int NKT = D_MODEL / 32;   // 32
    for (int kt = 0; kt < NKT; kt++) {
        if (kt + 1 < NKT) {
            issue_stage(su, (kt + 1) & 1, (kt + 1) * 32, tid, bm, bn, Ah, Al, Bh, Bl);
            CP_WAIT1();
        } else {
            CP_WAIT0();
        }
        __syncthreads();
        uint32_t sb = su + (uint32_t)(kt & 1) * STAGEB;

        #pragma unroll
        for (int ks = 0; ks < 32; ks += 16) {
            uint32_t a_h[4][4], a_l[4][4], b_h[2][4], b_l[2][4];
            #pragma unroll
            for (int mt = 0; mt < 4; mt++) {
                uint32_t off = (uint32_t)((wm + mt * 16 + (lane & 15)) * 40
                                          + ks + ((lane >> 4) << 3)) * 2;
                LDMX4(a_h[mt], sb + 0u * ABYTES + off);
                LDMX4(a_l[mt], sb + 1u * ABYTES + off);
            }
            #pragma unroll
            for (int p = 0; p < 2; p++) {
                int rb = wn + p * 16 + (lane & 7) + ((lane >> 4) << 3);
                int ce = ks + (((lane >> 3) & 1) << 3);
                uint32_t off = (uint32_t)(rb * 40 + ce) * 2;
                LDMX4(b_h[p], sb + 2u * ABYTES + off);
                LDMX4(b_l[p], sb + 3u * ABYTES + off);
            }
            #pragma unroll
            for (int mt = 0; mt < 4; mt++)
                #pragma unroll
                for (int nt = 0; nt < 4; nt++) {
                    int p = nt >> 1, q = (nt & 1) * 2;
                    mma16816(acc[mt][nt], a_h[mt], b_h[p][q], b_h[p][q + 1]);
                    mma16816(acc[mt][nt], a_h[mt], b_l[p][q], b_l[p][q + 1]);
                    mma16816(acc[mt][nt], a_l[mt], b_h[p][q], b_h[p][q + 1]);
                }
        }
        __syncthreads();
    }

    // Epilogue: direct register -> global (+bias)
    #pragma unroll
    for (int mt = 0; mt < 4; mt++) {
        int m0 = bm + wm + mt * 16 + (lane >> 2);
        #pragma unroll
        for (int nt = 0; nt < 4; nt++) {
            int n = bn + wn + nt * 8 + (lane & 3) * 2;
            float bx = bias[n], by = bias[n + 1];
            float2 v0 = make_float2(acc[mt][nt][0] + bx, acc[mt][nt][1] + by);
            float2 v1 = make_float2(acc[mt][nt][2] + bx, acc[mt][nt][3] + by);
            st_out(C, split, m0, n, v0);
            st_out(C, split, m0 + 8, n, v1);
        }
    }
}

// ---------------------------------------------------------------------------
// Flash attention, fp32 (unchanged, known good: 669us)
// ---------------------------------------------------------------------------
#define PADT 68

__global__ __launch_bounds__(256) void attn_kernel(
    const float* __restrict__ Qa, const float* __restrict__ Ka,
    const float* __restrict__ Va, float* __restrict__ ctx)
{
    extern __shared__ float sm[];
    float* QsT = sm;
    float* KsT = sm + 64 * PADT;
    float* Vs  = sm + 2 * 64 * PADT;
    float* Ps  = sm + 3 * 64 * PADT;

    const int qt = blockIdx.x;
    const int h  = blockIdx.y;
    const int b  = blockIdx.z;
    const int bh = b * NHEADS + h;
    const float* Qg = Qa + (size_t)bh * SEQ * HD;
    const float* Kg = Ka + (size_t)bh * SEQ * HD;
    const float* Vg = Va + (size_t)bh * SEQ * HD;

    const int tid = threadIdx.x;
    const int ty = tid >> 4;
    const int tx = tid & 15;
    const int q0 = qt * 64;
    const float scale = 0.125f;

    #pragma unroll
    for (int l = 0; l < 4; l++) {
        int idx = tid + l * 256;
        int r = idx >> 4;
        int c = (idx & 15) * 4;
        float4 qv = *(const float4*)(Qg + (size_t)(q0 + r) * HD + c);
        QsT[(c + 0) * PADT + r] = qv.x * scale;
        QsT[(c + 1) * PADT + r] = qv.y * scale;
        QsT[(c + 2) * PADT + r] = qv.z * scale;
        QsT[(c + 3) * PADT + r] = qv.w * scale;
    }

    float m_i[4], l_i[4], o[4][4];
    #pragma unroll
    for (int i = 0; i < 4; i++) {
        m_i[i] = -1e30f;
        l_i[i] = 0.0f;
        #pragma unroll
        for (int j = 0; j < 4; j++) o[i][j] = 0.0f;
    }

    for (int j0 = 0; j0 <= q0; j0 += 64) {
        __syncthreads();
        #pragma unroll
        for (int l = 0; l < 4; l++) {
            int idx = tid + l * 256;
            int r = idx >> 4;
            int c = (idx & 15) * 4;
            float4 kv = *(const float4*)(Kg + (size_t)(j0 + r) * HD + c);
            KsT[(c + 0) * PADT + r] = kv.x;
            KsT[(c + 1) * PADT + r] = kv.y;
            KsT[(c + 2) * PADT + r] = kv.z;
            KsT[(c + 3) * PADT + r] = kv.w;
            float4 vv = *(const float4*)(Vg + (size_t)(j0 + r) * HD + c);
            *(float4*)(Vs + r * PADT + c) = vv;
        }
        __syncthreads();

        float sc[4][4];
        #pragma unroll
        for (int i = 0; i < 4; i++)
            #pragma unroll
            for (int j = 0; j < 4; j++) sc[i][j] = 0.0f;

        #pragma unroll 4
        for (int k = 0; k < HD; k++) {
            float4 a = *(const float4*)(QsT + k * PADT + ty * 4);
            float4 bv = *(const float4*)(KsT + k * PADT + tx * 4);
            float av[4] = {a.x, a.y, a.z, a.w};
            float bb[4] = {bv.x, bv.y, bv.z, bv.w};
            #pragma unroll
            for (int i = 0; i < 4; i++)
                #pragma unroll
                for (int j = 0; j < 4; j++)
                    sc[i][j] += av[i] * bb[j];
        }

        if (j0 == q0) {
            #pragma unroll
            for (int i = 0; i < 4; i++)
                #pragma unroll
                for (int j = 0; j < 4; j++)
                    if (tx * 4 + j > ty * 4 + i) sc[i][j] = -1e30f;
        }

        #pragma unroll
        for (int i = 0; i < 4; i++) {
            float mx = fmaxf(fmaxf(sc[i][0], sc[i][1]), fmaxf(sc[i][2], sc[i][3]));
            #pragma unroll
            for (int off = 8; off > 0; off >>= 1)
                mx = fmaxf(mx, __shfl_xor_sync(0xffffffffu, mx, off));
            float mnew = fmaxf(m_i[i], mx);
            float corr = __expf(m_i[i] - mnew);
            float p0 = __expf(sc[i][0] - mnew);
            float p1 = __expf(sc[i][1] - mnew);
            float p2 = __expf(sc[i][2] - mnew);
            float p3 = __expf(sc[i][3] - mnew);
            float rs = p0 + p1 + p2 + p3;
            #pragma unroll
            for (int off = 8; off > 0; off >>= 1)
                rs += __shfl_xor_sync(0xffffffffu, rs, off);
            l_i[i] = l_i[i] * corr + rs;
            m_i[i] = mnew;
            #pragma unroll
            for (int j = 0; j < 4; j++) o[i][j] *= corr;
            float4 pv = make_float4(p0, p1, p2, p3);
            *(float4*)(Ps + (ty * 4 + i) * PADT + tx * 4) = pv;
        }
        __syncthreads();

        #pragma unroll 4
        for (int k = 0; k < 64; k++) {
            float4 vv = *(const float4*)(Vs + k * PADT + tx * 4);
            float p0 = Ps[(ty * 4 + 0) * PADT + k];
            float p1 = Ps[(ty * 4 + 1) * PADT + k];
            float p2 = Ps[(ty * 4 + 2) * PADT + k];
            float p3 = Ps[(ty * 4 + 3) * PADT + k];
            o[0][0] += p0 * vv.x; o[0][1] += p0 * vv.y; o[0][2] += p0 * vv.z; o[0][3] += p0 * vv.w;
            o[1][0] += p1 * vv.x; o[1][1] += p1 * vv.y; o[1][2] += p1 * vv.z; o[1][3] += p1 * vv.w;
            o[2][0] += p2 * vv.x; o[2][1] += p2 * vv.y; o[2][2] += p2 * vv.z; o[2][3] += p2 * vv.w;
            o[3][0] += p3 * vv.x; o[3][1] += p3 * vv.y; o[3][2] += p3 * vv.z; o[3][3] += p3 * vv.w;
        }
    }

    #pragma unroll
    for (int i = 0; i < 4; i++) {
        float inv = 1.0f / l_i[i];
        int tok = b * SEQ + q0 + ty * 4 + i;
        float4 ov;
        ov.x = o[i][0] * inv;
        ov.y = o[i][1] * inv;
        ov.z = o[i][2] * inv;
        ov.w = o[i][3] * inv;
        *(float4*)(ctx + (size_t)tok * D_MODEL + h * HD + tx * 4) = ov;
    }
}

// ---------------------------------------------------------------------------
extern "C" void kernel_launch(void* const* d_in, const int* in_sizes, int n_in,
                              void* d_out, int out_size)
{
    const float* x  = (const float*)d_in[0];
    const float* Wq = (const float*)d_in[1];
    const float* bq = (const float*)d_in[2];
    const float* Wk = (const float*)d_in[3];
    const float* bk = (const float*)d_in[4];
    const float* Wv = (const float*)d_in[5];
    const float* bv = (const float*)d_in[6];
    const float* Wo = (const float*)d_in[7];
    const float* bo = (const float*)d_in[8];
    float* out = (float*)d_out;

    float *qp, *kp, *vp, *cp;
    __nv_bfloat16 *xh, *xl, *cth, *ctl, *wh, *wl;
    cudaGetSymbolAddress((void**)&qp, g_q);
    cudaGetSymbolAddress((void**)&kp, g_k);
    cudaGetSymbolAddress((void**)&vp, g_v);
    cudaGetSymbolAddress((void**)&cp, g_ctx);
    cudaGetSymbolAddress((void**)&xh, g_xh);
    cudaGetSymbolAddress((void**)&xl, g_xl);
    cudaGetSymbolAddress((void**)&cth, g_cth);
    cudaGetSymbolAddress((void**)&ctl, g_ctl);
    cudaGetSymbolAddress((void**)&wh, g_wh);
    cudaGetSymbolAddress((void**)&wl, g_wl);

    const size_t WSZ = (size_t)D_MODEL * D_MODEL;

    split_kernel<<<1024, 256>>>(x, xh, xl, NTOK * D_MODEL);
    dim3 tg(32, 32), tb(32, 8);
    tsplit_kernel<<<tg, tb>>>(Wq, wh + 0 * WSZ, wl + 0 * WSZ);
    tsplit_kernel<<<tg, tb>>>(Wk, wh + 1 * WSZ, wl + 1 * WSZ);
    tsplit_kernel<<<tg, tb>>>(Wv, wh + 2 * WSZ, wl + 2 * WSZ);
    tsplit_kernel<<<tg, tb>>>(Wo, wh + 3 * WSZ, wl + 3 * WSZ);

    cudaFuncSetAttribute(gemm_mma, cudaFuncAttributeMaxDynamicSharedMemorySize, SMEM_GEMM);
    dim3 gg(D_MODEL / 128, NTOK / 128);   // (8, 32)
    gemm_mma<<<gg, 256, SMEM_GEMM>>>(xh, xl, wh + 0 * WSZ, wl + 0 * WSZ, bq, qp, 1);
    gemm_mma<<<gg, 256, SMEM_GEMM>>>(xh, xl, wh + 1 * WSZ, wl + 1 * WSZ, bk, kp, 1);
    gemm_mma<<<gg, 256, SMEM_GEMM>>>(xh, xl, wh + 2 * WSZ, wl + 2 * WSZ, bv, vp, 1);

    int smem = 4 * 64 * PADT * sizeof(float);
    cudaFuncSetAttribute(attn_kernel, cudaFuncAttributeMaxDynamicSharedMemorySize, smem);
    dim3 ga(SEQ / 64, NHEADS, BATCH);
    attn_kernel<<<ga, 256, smem>>>(qp, kp, vp, cp);

    split_kernel<<<1024, 256>>>(cp, cth, ctl, NTOK * D_MODEL);
    gemm_mma<<<gg, 256, SMEM_GEMM>>>(cth, ctl, wh + 3 * WSZ, wl + 3 * WSZ, bo, out, 0);
}

// round 4
// speedup vs baseline: 2.6219x; 1.7245x over previous
#include <cuda_runtime.h>
#include <cuda_bf16.h>
#include <cstdint>
#include <math.h>

#define D_MODEL 1024
#define NHEADS 16
#define HD 64
#define BATCH 2
#define SEQ 2048
#define NTOK (BATCH * SEQ)   // 4096

typedef __nv_bfloat16 bf16;

// ---------------------------------------------------------------------------
// Scratch (no allocations allowed)
// ---------------------------------------------------------------------------
__device__ bf16 g_xh[(size_t)NTOK * D_MODEL];
__device__ bf16 g_xl[(size_t)NTOK * D_MODEL];
__device__ bf16 g_qh[(size_t)NTOK * D_MODEL];   // [B,H,S,hd] hi (scaled by 1/8)
__device__ bf16 g_ql[(size_t)NTOK * D_MODEL];
__device__ bf16 g_kh[(size_t)NTOK * D_MODEL];
__device__ bf16 g_kl[(size_t)NTOK * D_MODEL];
__device__ bf16 g_vh[(size_t)NTOK * D_MODEL];
__device__ bf16 g_vl[(size_t)NTOK * D_MODEL];
__device__ bf16 g_cth[(size_t)NTOK * D_MODEL];  // ctx hi/lo, flat [B*S][D]
__device__ bf16 g_ctl[(size_t)NTOK * D_MODEL];
__device__ bf16 g_wh[(size_t)4 * D_MODEL * D_MODEL];  // weights transposed [n][k]
__device__ bf16 g_wl[(size_t)4 * D_MODEL * D_MODEL];

// ---------------------------------------------------------------------------
// Helpers (generic sm_80+ PTX only)
// ---------------------------------------------------------------------------
__device__ __forceinline__ uint32_t smem_u32(const void* p) {
    uint32_t a;
    asm("{ .reg .u64 t; cvta.to.shared.u64 t, %1; cvt.u32.u64 %0, t; }" : "=r"(a) : "l"(p));
    return a;
}
__device__ __forceinline__ void cpa16(uint32_t s, const void* g) {
    asm volatile("cp.async.cg.shared.global [%0], [%1], 16;" :: "r"(s), "l"(g));
}
#define CP_COMMIT() asm volatile("cp.async.commit_group;" ::: "memory")
#define CP_WAIT1()  asm volatile("cp.async.wait_group 1;" ::: "memory")
#define CP_WAIT0()  asm volatile("cp.async.wait_group 0;" ::: "memory")

#define LDMX4(r, a) \
    asm volatile("ldmatrix.sync.aligned.m8n8.x4.shared.b16 {%0,%1,%2,%3}, [%4];" \
        : "=r"((r)[0]), "=r"((r)[1]), "=r"((r)[2]), "=r"((r)[3]) : "r"(a))
#define LDMX4T(r, a) \
    asm volatile("ldmatrix.sync.aligned.m8n8.x4.trans.shared.b16 {%0,%1,%2,%3}, [%4];" \
        : "=r"((r)[0]), "=r"((r)[1]), "=r"((r)[2]), "=r"((r)[3]) : "r"(a))

__device__ __forceinline__ void mma16816(float* c, const uint32_t* a, uint32_t b0, uint32_t b1) {
    asm volatile(
        "mma.sync.aligned.m16n8k16.row.col.f32.bf16.bf16.f32 "
        "{%0,%1,%2,%3}, {%4,%5,%6,%7}, {%8,%9}, {%0,%1,%2,%3};"
        : "+f"(c[0]), "+f"(c[1]), "+f"(c[2]), "+f"(c[3])
        : "r"(a[0]), "r"(a[1]), "r"(a[2]), "r"(a[3]), "r"(b0), "r"(b1));
}

// pack two fp32 -> bf16x2 reg (lo = first elem)
__device__ __forceinline__ uint32_t packbf(float lo, float hi) {
    uint32_t r;
    asm("cvt.rn.bf16x2.f32 %0, %1, %2;" : "=r"(r) : "f"(hi), "f"(lo));
    return r;
}
__device__ __forceinline__ float2 unpackbf(uint32_t u) {
    __nv_bfloat162 b = *(__nv_bfloat162*)&u;
    return make_float2(__bfloat162float(b.x), __bfloat162float(b.y));
}

// ---------------------------------------------------------------------------
// Conversion kernels
// ---------------------------------------------------------------------------
__global__ void split_kernel(const float* __restrict__ s, bf16* __restrict__ h,
                             bf16* __restrict__ l, int n) {
    int i = blockIdx.x * blockDim.x + threadIdx.x;
    int stride = gridDim.x * blockDim.x;
    for (; i < n; i += stride) {
        float v = s[i];
        bf16 hi = __float2bfloat16(v);
        h[i] = hi;
        l[i] = __float2bfloat16(v - __bfloat162float(hi));
    }
}

// W [k][n] fp32 -> hi/lo [n][k] bf16
__global__ void tsplit_kernel(const float* __restrict__ W, bf16* __restrict__ th,
                              bf16* __restrict__ tl) {
    __shared__ float t[32][33];
    int n0 = blockIdx.x * 32, k0 = blockIdx.y * 32;
    int x = threadIdx.x, y = threadIdx.y;  // 32x8
    #pragma unroll
    for (int j = 0; j < 32; j += 8)
        t[y + j][x] = W[(size_t)(k0 + y + j) * D_MODEL + n0 + x];
    __syncthreads();
    #pragma unroll
    for (int j = 0; j < 32; j += 8) {
        float v = t[x][y + j];
        bf16 hi = __float2bfloat16(v);
        size_t o = (size_t)(n0 + y + j) * D_MODEL + k0 + x;
        th[o] = hi;
        tl[o] = __float2bfloat16(v - __bfloat162float(hi));
    }
}

// ---------------------------------------------------------------------------
// mma.sync GEMM: C[4096,1024] = A @ B^T (+bias)*scale
// mode 0: fp32 flat out; mode 1: bf16 hi/lo head-split [B,H,S,hd] out
// ---------------------------------------------------------------------------
#define ABYTES 10240u
#define STAGEB (4u * ABYTES)
#define SMEM_GEMM (2u * STAGEB)

__device__ __forceinline__ void issue_stage(
    uint32_t su, int stage, int k0, int tid, int bm, int bn,
    const bf16* __restrict__ Ah, const bf16* __restrict__ Al,
    const bf16* __restrict__ Bh, const bf16* __restrict__ Bl)
{
    uint32_t sb = su + (uint32_t)stage * STAGEB;
    #pragma unroll
    for (int j = 0; j < 2; j++) {
        int idx = tid + j * 256;
        int r = idx >> 2, c8 = idx & 3;
        uint32_t so = (uint32_t)(r * 40 + c8 * 8) * 2;
        size_t goA = (size_t)(bm + r) * D_MODEL + k0 + c8 * 8;
        size_t goB = (size_t)(bn + r) * D_MODEL + k0 + c8 * 8;
        cpa16(sb + 0u * ABYTES + so, Ah + goA);
        cpa16(sb + 1u * ABYTES + so, Al + goA);
        cpa16(sb + 2u * ABYTES + so, Bh + goB);
        cpa16(sb + 3u * ABYTES + so, Bl + goB);
    }
    CP_COMMIT();
}

__global__ __launch_bounds__(256) void gemm_mma(
    const bf16* __restrict__ Ah, const bf16* __restrict__ Al,
    const bf16* __restrict__ Bh, const bf16* __restrict__ Bl,
    const float* __restrict__ bias, float* __restrict__ Cf,
    bf16* __restrict__ Ch, bf16* __restrict__ Cl, int mode, float scale)
{
    extern __shared__ char smraw[];
    const uint32_t su = smem_u32(smraw);
    const int tid = threadIdx.x, lane = tid & 31, wid = tid >> 5;
    const int bm = blockIdx.y * 128, bn = blockIdx.x * 128;
    const int wm = (wid >> 2) * 64, wn = (wid & 3) * 32;

    float acc[4][4][4];
    #pragma unroll
    for (int i = 0; i < 4; i++)
        #pragma unroll
        for (int j = 0; j < 4; j++)
            #pragma unroll
            for (int q = 0; q < 4; q++) acc[i][j][q] = 0.0f;

    issue_stage(su, 0, 0, tid, bm, bn, Ah, Al, Bh, Bl);

    const int NKT = D_MODEL / 32;
    for (int kt = 0; kt < NKT; kt++) {
        if (kt + 1 < NKT) {
            issue_stage(su, (kt + 1) & 1, (kt + 1) * 32, tid, bm, bn, Ah, Al, Bh, Bl);
            CP_WAIT1();
        } else {
            CP_WAIT0();
        }
        __syncthreads();
        uint32_t sb = su + (uint32_t)(kt & 1) * STAGEB;

        #pragma unroll
        for (int ks = 0; ks < 32; ks += 16) {
            uint32_t a_h[4][4], a_l[4][4], b_h[2][4], b_l[2][4];
            #pragma unroll
            for (int mt = 0; mt < 4; mt++) {
                uint32_t off = (uint32_t)((wm + mt * 16 + (lane & 15)) * 40
                                          + ks + ((lane >> 4) << 3)) * 2;
                LDMX4(a_h[mt], sb + 0u * ABYTES + off);
                LDMX4(a_l[mt], sb + 1u * ABYTES + off);
            }
            #pragma unroll
            for (int p = 0; p < 2; p++) {
                int rb = wn + p * 16 + (lane & 7) + ((lane >> 4) << 3);
                int ce = ks + (((lane >> 3) & 1) << 3);
                uint32_t off = (uint32_t)(rb * 40 + ce) * 2;
                LDMX4(b_h[p], sb + 2u * ABYTES + off);
                LDMX4(b_l[p], sb + 3u * ABYTES + off);
            }
            #pragma unroll
            for (int mt = 0; mt < 4; mt++)
                #pragma unroll
                for (int nt = 0; nt < 4; nt++) {
                    int p = nt >> 1, q = (nt & 1) * 2;
                    mma16816(acc[mt][nt], a_h[mt], b_h[p][q], b_h[p][q + 1]);
                    mma16816(acc[mt][nt], a_h[mt], b_l[p][q], b_l[p][q + 1]);
                    mma16816(acc[mt][nt], a_l[mt], b_h[p][q], b_h[p][q + 1]);
                }
        }
        __syncthreads();
    }

    #pragma unroll
    for (int mt = 0; mt < 4; mt++) {
        int m0 = bm + wm + mt * 16 + (lane >> 2);
        #pragma unroll
        for (int nt = 0; nt < 4; nt++) {
            int n = bn + wn + nt * 8 + (lane & 3) * 2;
            float bx = bias[n], by = bias[n + 1];
            float v0 = (acc[mt][nt][0] + bx) * scale;
            float v1 = (acc[mt][nt][1] + by) * scale;
            float v2 = (acc[mt][nt][2] + bx) * scale;
            float v3 = (acc[mt][nt][3] + by) * scale;
            if (mode) {
                #pragma unroll
                for (int rr = 0; rr < 2; rr++) {
                    int m = m0 + rr * 8;
                    float a = rr ? v2 : v0, b = rr ? v3 : v1;
                    int bb = m >> 11, ss = m & 2047, hh = n >> 6, dd = n & 63;
                    size_t o = (((size_t)(bb * NHEADS + hh) * SEQ + ss) * HD + dd);
                    uint32_t uh = packbf(a, b);
                    float2 f = unpackbf(uh);
                    uint32_t ul = packbf(a - f.x, b - f.y);
                    *(uint32_t*)(Ch + o) = uh;
                    *(uint32_t*)(Cl + o) = ul;
                }
            } else {
                *(float2*)(Cf + (size_t)m0 * D_MODEL + n) = make_float2(v0, v1);
                *(float2*)(Cf + (size_t)(m0 + 8) * D_MODEL + n) = make_float2(v2, v3);
            }
        }
    }
}

// ---------------------------------------------------------------------------
// FA2-style mma attention. BQ=128 (8 warps x 16 rows), BKV=64.
// Split-bf16: S = QhKh + QhKl + QlKh; O += PhVh + PhVl + PlVh.
// smem rows padded to 144B. K/V double-buffered cp.async.
// ---------------------------------------------------------------------------
#define ROWB 144u            // 72 elems * 2B
#define Q_BYTES (128u * ROWB)      // 18432
#define KV_ARR (64u * ROWB)        // 9216
#define KV_STAGE (4u * KV_ARR)     // 36864: Kh,Kl,Vh,Vl
#define SMEM_ATTN (2u * Q_BYTES + 2u * KV_STAGE)   // 110592

__device__ __forceinline__ void attn_issue_kv(
    uint32_t sb, const bf16* __restrict__ kh, const bf16* __restrict__ kl,
    const bf16* __restrict__ vh, const bf16* __restrict__ vl,
    size_t gbase, int j0, int tid)
{
    #pragma unroll
    for (int i = 0; i < 2; i++) {
        int c = tid + i * 256;
        int r = c >> 3, u = c & 7;
        uint32_t so = (uint32_t)r * ROWB + (uint32_t)u * 16u;
        size_t go = gbase + (size_t)(j0 + r) * HD + u * 8;
        cpa16(sb + 0u * KV_ARR + so, kh + go);
        cpa16(sb + 1u * KV_ARR + so, kl + go);
        cpa16(sb + 2u * KV_ARR + so, vh + go);
        cpa16(sb + 3u * KV_ARR + so, vl + go);
    }
    CP_COMMIT();
}

__global__ __launch_bounds__(256) void attn_mma(
    const bf16* __restrict__ qh, const bf16* __restrict__ ql,
    const bf16* __restrict__ kh, const bf16* __restrict__ kl,
    const bf16* __restrict__ vh, const bf16* __restrict__ vl,
    bf16* __restrict__ cth, bf16* __restrict__ ctl)
{
    extern __shared__ char smraw[];
    const uint32_t su = smem_u32(smraw);
    const uint32_t Qh_s = su, Ql_s = su + Q_BYTES;
    const uint32_t KV0 = su + 2u * Q_BYTES;

    const int qt = (gridDim.x - 1) - blockIdx.x;   // heavy tiles first
    const int h = blockIdx.y, b = blockIdx.z;
    const int bh = b * NHEADS + h;
    const size_t gbase = (size_t)bh * SEQ * HD;
    const int q0 = qt * 128;
    const int ntiles = 2 * qt + 2;

    const int tid = threadIdx.x, lane = tid & 31, wid = tid >> 5;
    const int wm = wid * 16;
    const int qr = q0 + wm;

    // Q load (hi/lo), 4 chunks per thread per array
    #pragma unroll
    for (int i = 0; i < 4; i++) {
        int c = tid + i * 256;
        int r = c >> 3, u = c & 7;
        uint32_t so = (uint32_t)r * ROWB + (uint32_t)u * 16u;
        size_t go = gbase + (size_t)(q0 + r) * HD + u * 8;
        cpa16(Qh_s + so, qh + go);
        cpa16(Ql_s + so, ql + go);
    }
    attn_issue_kv(KV0, kh, kl, vh, vl, gbase, 0, tid);      // group 0 (with Q)
    if (ntiles > 1) attn_issue_kv(KV0 + KV_STAGE, kh, kl, vh, vl, gbase, 64, tid);

    float o[8][4];
    #pragma unroll
    for (int nt = 0; nt < 8; nt++)
        #pragma unroll
        for (int q = 0; q < 4; q++) o[nt][q] = 0.0f;
    float m0 = -1e30f, m1 = -1e30f, l0 = 0.0f, l1 = 0.0f;

    for (int t = 0; t < ntiles; t++) {
        if (t + 1 < ntiles) CP_WAIT1(); else CP_WAIT0();
        __syncthreads();
        const int j0 = t * 64;
        const uint32_t sb = KV0 + (uint32_t)(t & 1) * KV_STAGE;
        const uint32_t kh_s = sb, kl_s = sb + KV_ARR;
        const uint32_t vh_s = sb + 2u * KV_ARR, vl_s = sb + 3u * KV_ARR;

        // ---- S = Q K^T ----
        float s[8][4];
        #pragma unroll
        for (int nt = 0; nt < 8; nt++)
            #pragma unroll
            for (int q = 0; q < 4; q++) s[nt][q] = 0.0f;

        #pragma unroll
        for (int ks = 0; ks < 4; ks++) {
            uint32_t ah[4], al[4];
            {
                uint32_t off = (uint32_t)(wm + (lane & 15)) * ROWB
                             + (uint32_t)(ks * 16 + ((lane >> 4) << 3)) * 2u;
                LDMX4(ah, Qh_s + off);
                LDMX4(al, Ql_s + off);
            }
            #pragma unroll
            for (int np = 0; np < 4; np++) {
                int rk = np * 16 + ((lane >> 4) << 3) + (lane & 7);
                uint32_t off = (uint32_t)rk * ROWB
                             + (uint32_t)(ks * 16 + (((lane >> 3) & 1) << 3)) * 2u;
                uint32_t bhf[4], blf[4];
                LDMX4(bhf, kh_s + off);
                LDMX4(blf, kl_s + off);
                #pragma unroll
                for (int q2 = 0; q2 < 2; q2++) {
                    int nt = np * 2 + q2;
                    mma16816(s[nt], ah, bhf[q2 * 2], bhf[q2 * 2 + 1]);
                    mma16816(s[nt], ah, blf[q2 * 2], blf[q2 * 2 + 1]);
                    mma16816(s[nt], al, bhf[q2 * 2], bhf[q2 * 2 + 1]);
                }
            }
        }

        // ---- causal mask ----
        if (j0 + 63 > qr) {
            int r0 = qr + (lane >> 2), r1 = r0 + 8;
            #pragma unroll
            for (int nt = 0; nt < 8; nt++)
                #pragma unroll
                for (int c = 0; c < 2; c++) {
                    int k = j0 + nt * 8 + (lane & 3) * 2 + c;
                    if (k > r0) s[nt][c] = -1e30f;
                    if (k > r1) s[nt][2 + c] = -1e30f;
                }
        }

        // ---- online softmax ----
        float mx0 = -1e30f, mx1 = -1e30f;
        #pragma unroll
        for (int nt = 0; nt < 8; nt++) {
            mx0 = fmaxf(mx0, fmaxf(s[nt][0], s[nt][1]));
            mx1 = fmaxf(mx1, fmaxf(s[nt][2], s[nt][3]));
        }
        mx0 = fmaxf(mx0, __shfl_xor_sync(0xffffffffu, mx0, 1));
        mx0 = fmaxf(mx0, __shfl_xor_sync(0xffffffffu, mx0, 2));
        mx1 = fmaxf(mx1, __shfl_xor_sync(0xffffffffu, mx1, 1));
        mx1 = fmaxf(mx1, __shfl_xor_sync(0xffffffffu, mx1, 2));
        float mn0 = fmaxf(m0, mx0), mn1 = fmaxf(m1, mx1);
        float c0 = __expf(m0 - mn0), c1 = __expf(m1 - mn1);
        float sum0 = 0.0f, sum1 = 0.0f;
        #pragma unroll
        for (int nt = 0; nt < 8; nt++) {
            s[nt][0] = __expf(s[nt][0] - mn0);
            s[nt][1] = __expf(s[nt][1] - mn0);
            s[nt][2] = __expf(s[nt][2] - mn1);
            s[nt][3] = __expf(s[nt][3] - mn1);
            sum0 += s[nt][0] + s[nt][1];
            sum1 += s[nt][2] + s[nt][3];
        }
        sum0 += __shfl_xor_sync(0xffffffffu, sum0, 1);
        sum0 += __shfl_xor_sync(0xffffffffu, sum0, 2);
        sum1 += __shfl_xor_sync(0xffffffffu, sum1, 1);
        sum1 += __shfl_xor_sync(0xffffffffu, sum1, 2);
        l0 = l0 * c0 + sum0;
        l1 = l1 * c1 + sum1;
        m0 = mn0; m1 = mn1;
        #pragma unroll
        for (int nt = 0; nt < 8; nt++) {
            o[nt][0] *= c0; o[nt][1] *= c0;
            o[nt][2] *= c1; o[nt][3] *= c1;
        }

        // ---- O += P V ----
        #pragma unroll
        for (int kb = 0; kb < 4; kb++) {
            uint32_t Aph[4], Apl[4];
            #pragma unroll
            for (int half = 0; half < 2; half++) {
                int nt = kb * 2 + half;
                uint32_t u0 = packbf(s[nt][0], s[nt][1]);
                float2 f0 = unpackbf(u0);
                uint32_t u1 = packbf(s[nt][2], s[nt][3]);
                float2 f1 = unpackbf(u1);
                Aph[half * 2 + 0] = u0;
                Aph[half * 2 + 1] = u1;
                Apl[half * 2 + 0] = packbf(s[nt][0] - f0.x, s[nt][1] - f0.y);
                Apl[half * 2 + 1] = packbf(s[nt][2] - f1.x, s[nt][3] - f1.y);
            }
            #pragma unroll
            for (int np = 0; np < 4; np++) {
                int rv = kb * 16 + (((lane >> 3) & 1) << 3) + (lane & 7);
                int cv = np * 16 + ((lane >> 4) << 3);
                uint32_t off = (uint32_t)rv * ROWB + (uint32_t)cv * 2u;
                uint32_t vhf[4], vlf[4];
                LDMX4T(vhf, vh_s + off);
                LDMX4T(vlf, vl_s + off);
                #pragma unroll
                for (int q2 = 0; q2 < 2; q2++) {
                    int nt = np * 2 + q2;
                    mma16816(o[nt], Aph, vhf[q2 * 2], vhf[q2 * 2 + 1]);
                    mma16816(o[nt], Aph, vlf[q2 * 2], vlf[q2 * 2 + 1]);
                    mma16816(o[nt], Apl, vhf[q2 * 2], vhf[q2 * 2 + 1]);
                }
            }
        }

        __syncthreads();
        if (t + 2 < ntiles)
            attn_issue_kv(KV0 + (uint32_t)(t & 1) * KV_STAGE, kh, kl, vh, vl,
                          gbase, (t + 2) * 64, tid);
    }

    // ---- epilogue: normalize, split hi/lo, write ctx ----
    float inv0 = 1.0f / l0, inv1 = 1.0f / l1;
    int r0 = qr + (lane >> 2);
    size_t tok0 = (size_t)(b * SEQ + r0) * D_MODEL + h * HD;
    size_t tok1 = tok0 + 8 * D_MODEL;
    #pragma unroll
    for (int nt = 0; nt < 8; nt++) {
        int col = nt * 8 + (lane & 3) * 2;
        float a0 = o[nt][0] * inv0, a1 = o[nt][1] * inv0;
        uint32_t uh0 = packbf(a0, a1);
        float2 f0 = unpackbf(uh0);
        *(uint32_t*)(cth + tok0 + col) = uh0;
        *(uint32_t*)(ctl + tok0 + col) = packbf(a0 - f0.x, a1 - f0.y);
        float b0 = o[nt][2] * inv1, b1 = o[nt][3] * inv1;
        uint32_t uh1 = packbf(b0, b1);
        float2 f1 = unpackbf(uh1);
        *(uint32_t*)(cth + tok1 + col) = uh1;
        *(uint32_t*)(ctl + tok1 + col) = packbf(b0 - f1.x, b1 - f1.y);
    }
}

// ---------------------------------------------------------------------------
extern "C" void kernel_launch(void* const* d_in, const int* in_sizes, int n_in,
                              void* d_out, int out_size)
{
    const float* x  = (const float*)d_in[0];
    const float* Wq = (const float*)d_in[1];
    const float* bq = (const float*)d_in[2];
    const float* Wk = (const float*)d_in[3];
    const float* bk = (const float*)d_in[4];
    const float* Wv = (const float*)d_in[5];
    const float* bv = (const float*)d_in[6];
    const float* Wo = (const float*)d_in[7];
    const float* bo = (const float*)d_in[8];
    float* out = (float*)d_out;

    bf16 *xh, *xl, *qhp, *qlp, *khp, *klp, *vhp, *vlp, *cth, *ctl, *wh, *wl;
    cudaGetSymbolAddress((void**)&xh, g_xh);
    cudaGetSymbolAddress((void**)&xl, g_xl);
    cudaGetSymbolAddress((void**)&qhp, g_qh);
    cudaGetSymbolAddress((void**)&qlp, g_ql);
    cudaGetSymbolAddress((void**)&khp, g_kh);
    cudaGetSymbolAddress((void**)&klp, g_kl);
    cudaGetSymbolAddress((void**)&vhp, g_vh);
    cudaGetSymbolAddress((void**)&vlp, g_vl);
    cudaGetSymbolAddress((void**)&cth, g_cth);
    cudaGetSymbolAddress((void**)&ctl, g_ctl);
    cudaGetSymbolAddress((void**)&wh, g_wh);
    cudaGetSymbolAddress((void**)&wl, g_wl);

    const size_t WSZ = (size_t)D_MODEL * D_MODEL;

    split_kernel<<<1024, 256>>>(x, xh, xl, NTOK * D_MODEL);
    dim3 tg(32, 32), tb(32, 8);
    tsplit_kernel<<<tg, tb>>>(Wq, wh + 0 * WSZ, wl + 0 * WSZ);
    tsplit_kernel<<<tg, tb>>>(Wk, wh + 1 * WSZ, wl + 1 * WSZ);
    tsplit_kernel<<<tg, tb>>>(Wv, wh + 2 * WSZ, wl + 2 * WSZ);
    tsplit_kernel<<<tg, tb>>>(Wo, wh + 3 * WSZ, wl + 3 * WSZ);

    cudaFuncSetAttribute(gemm_mma, cudaFuncAttributeMaxDynamicSharedMemorySize, SMEM_GEMM);
    dim3 gg(D_MODEL / 128, NTOK / 128);
    gemm_mma<<<gg, 256, SMEM_GEMM>>>(xh, xl, wh + 0 * WSZ, wl + 0 * WSZ, bq,
                                     nullptr, qhp, qlp, 1, 0.125f);
    gemm_mma<<<gg, 256, SMEM_GEMM>>>(xh, xl, wh + 1 * WSZ, wl + 1 * WSZ, bk,
                                     nullptr, khp, klp, 1, 1.0f);
    gemm_mma<<<gg, 256, SMEM_GEMM>>>(xh, xl, wh + 2 * WSZ, wl + 2 * WSZ, bv,
                                     nullptr, vhp, vlp, 1, 1.0f);

    cudaFuncSetAttribute(attn_mma, cudaFuncAttributeMaxDynamicSharedMemorySize, SMEM_ATTN);
    dim3 ga(SEQ / 128, NHEADS, BATCH);   // (16, 16, 2)
    attn_mma<<<ga, 256, SMEM_ATTN>>>(qhp, qlp, khp, klp, vhp, vlp, cth, ctl);

    gemm_mma<<<gg, 256, SMEM_GEMM>>>(cth, ctl, wh + 3 * WSZ, wl + 3 * WSZ, bo,
                                     out, nullptr, nullptr, 0, 1.0f);
}

// round 6
// speedup vs baseline: 2.7077x; 1.0327x over previous
#include <cuda_runtime.h>
#include <cuda_bf16.h>
#include <cstdint>
#include <math.h>

#define D_MODEL 1024
#define NHEADS 16
#define HD 64
#define BATCH 2
#define SEQ 2048
#define NTOK (BATCH * SEQ)   // 4096

// Q pre-scale: (1/sqrt(64)) * log2(e)  -> scores already in log2 domain
#define QSCALE 0.180336875967866f

typedef __nv_bfloat16 bf16;

// ---------------------------------------------------------------------------
// Scratch (no allocations allowed)
// ---------------------------------------------------------------------------
__device__ bf16 g_xh[(size_t)NTOK * D_MODEL];
__device__ bf16 g_xl[(size_t)NTOK * D_MODEL];
__device__ bf16 g_qh[(size_t)NTOK * D_MODEL];   // [B,H,S,hd]
__device__ bf16 g_ql[(size_t)NTOK * D_MODEL];
__device__ bf16 g_kh[(size_t)NTOK * D_MODEL];
__device__ bf16 g_kl[(size_t)NTOK * D_MODEL];
__device__ bf16 g_vh[(size_t)NTOK * D_MODEL];
__device__ bf16 g_vl[(size_t)NTOK * D_MODEL];
__device__ bf16 g_cth[(size_t)NTOK * D_MODEL];
__device__ bf16 g_ctl[(size_t)NTOK * D_MODEL];
__device__ bf16 g_wh[(size_t)4 * D_MODEL * D_MODEL];  // [n][k] transposed
__device__ bf16 g_wl[(size_t)4 * D_MODEL * D_MODEL];

// ---------------------------------------------------------------------------
// Helpers (generic sm_80+ PTX only)
// ---------------------------------------------------------------------------
__device__ __forceinline__ uint32_t smem_u32(const void* p) {
    uint32_t a;
    asm("{ .reg .u64 t; cvta.to.shared.u64 t, %1; cvt.u32.u64 %0, t; }" : "=r"(a) : "l"(p));
    return a;
}
__device__ __forceinline__ void cpa16(uint32_t s, const void* g) {
    asm volatile("cp.async.cg.shared.global [%0], [%1], 16;" :: "r"(s), "l"(g));
}
#define CP_COMMIT() asm volatile("cp.async.commit_group;" ::: "memory")
#define CP_WAIT1()  asm volatile("cp.async.wait_group 1;" ::: "memory")
#define CP_WAIT0()  asm volatile("cp.async.wait_group 0;" ::: "memory")

#define LDMX4(r, a) \
    asm volatile("ldmatrix.sync.aligned.m8n8.x4.shared.b16 {%0,%1,%2,%3}, [%4];" \
        : "=r"((r)[0]), "=r"((r)[1]), "=r"((r)[2]), "=r"((r)[3]) : "r"(a))
#define LDMX4T(r, a) \
    asm volatile("ldmatrix.sync.aligned.m8n8.x4.trans.shared.b16 {%0,%1,%2,%3}, [%4];" \
        : "=r"((r)[0]), "=r"((r)[1]), "=r"((r)[2]), "=r"((r)[3]) : "r"(a))

__device__ __forceinline__ void mma16816(float* c, const uint32_t* a, uint32_t b0, uint32_t b1) {
    asm volatile(
        "mma.sync.aligned.m16n8k16.row.col.f32.bf16.bf16.f32 "
        "{%0,%1,%2,%3}, {%4,%5,%6,%7}, {%8,%9}, {%0,%1,%2,%3};"
        : "+f"(c[0]), "+f"(c[1]), "+f"(c[2]), "+f"(c[3])
        : "r"(a[0]), "r"(a[1]), "r"(a[2]), "r"(a[3]), "r"(b0), "r"(b1));
}

__device__ __forceinline__ uint32_t packbf(float lo, float hi) {
    uint32_t r;
    asm("cvt.rn.bf16x2.f32 %0, %1, %2;" : "=r"(r) : "f"(hi), "f"(lo));
    return r;
}
__device__ __forceinline__ float2 unpackbf(uint32_t u) {
    __nv_bfloat162 b = *(__nv_bfloat162*)&u;
    return make_float2(__bfloat162float(b.x), __bfloat162float(b.y));
}
__device__ __forceinline__ float ex2f(float x) {
    float y;
    asm("ex2.approx.f32 %0, %1;" : "=f"(y) : "f"(x));
    return y;
}

// ---------------------------------------------------------------------------
// Conversion kernels
// ---------------------------------------------------------------------------
__global__ void split_kernel(const float* __restrict__ s, bf16* __restrict__ h,
                             bf16* __restrict__ l, int n) {
    int i = blockIdx.x * blockDim.x + threadIdx.x;
    int stride = gridDim.x * blockDim.x;
    for (; i < n; i += stride) {
        float v = s[i];
        bf16 hi = __float2bfloat16(v);
        h[i] = hi;
        l[i] = __float2bfloat16(v - __bfloat162float(hi));
    }
}

__global__ void tsplit_kernel(const float* __restrict__ W, bf16* __restrict__ th,
                              bf16* __restrict__ tl) {
    __shared__ float t[32][33];
    int n0 = blockIdx.x * 32, k0 = blockIdx.y * 32;
    int x = threadIdx.x, y = threadIdx.y;  // 32x8
    #pragma unroll
    for (int j = 0; j < 32; j += 8)
        t[y + j][x] = W[(size_t)(k0 + y + j) * D_MODEL + n0 + x];
    __syncthreads();
    #pragma unroll
    for (int j = 0; j < 32; j += 8) {
        float v = t[x][y + j];
        bf16 hi = __float2bfloat16(v);
        size_t o = (size_t)(n0 + y + j) * D_MODEL + k0 + x;
        th[o] = hi;
        tl[o] = __float2bfloat16(v - __bfloat162float(hi));
    }
}

// ---------------------------------------------------------------------------
// Shared GEMM mainloop: acc[4][4][4] = A[128, D] @ B[128, D]^T  (split-bf16)
// ---------------------------------------------------------------------------
#define ABYTES 10240u
#define STAGEB (4u * ABYTES)
#define SMEM_GEMM (2u * STAGEB)

__device__ __forceinline__ void issue_stage(
    uint32_t su, int stage, int k0, int tid, int bm, int bn,
    const bf16* __restrict__ Ah, const bf16* __restrict__ Al,
    const bf16* __restrict__ Bh, const bf16* __restrict__ Bl)
{
    uint32_t sb = su + (uint32_t)stage * STAGEB;
    #pragma unroll
    for (int j = 0; j < 2; j++) {
        int idx = tid + j * 256;
        int r = idx >> 2, c8 = idx & 3;
        uint32_t so = (uint32_t)(r * 40 + c8 * 8) * 2;
        size_t goA = (size_t)(bm + r) * D_MODEL + k0 + c8 * 8;
        size_t goB = (size_t)(bn + r) * D_MODEL + k0 + c8 * 8;
        cpa16(sb + 0u * ABYTES + so, Ah + goA);
        cpa16(sb + 1u * ABYTES + so, Al + goA);
        cpa16(sb + 2u * ABYTES + so, Bh + goB);
        cpa16(sb + 3u * ABYTES + so, Bl + goB);
    }
    CP_COMMIT();
}

__device__ __forceinline__ void gemm_core(
    uint32_t su, int tid, int bm, int bn,
    const bf16* __restrict__ Ah, const bf16* __restrict__ Al,
    const bf16* __restrict__ Bh, const bf16* __restrict__ Bl,
    float acc[4][4][4])
{
    const int lane = tid & 31, wid = tid >> 5;
    const int wm = (wid >> 2) * 64, wn = (wid & 3) * 32;

    issue_stage(su, 0, 0, tid, bm, bn, Ah, Al, Bh, Bl);

    const int NKT = D_MODEL / 32;
    for (int kt = 0; kt < NKT; kt++) {
        if (kt + 1 < NKT) {
            issue_stage(su, (kt + 1) & 1, (kt + 1) * 32, tid, bm, bn, Ah, Al, Bh, Bl);
            CP_WAIT1();
        } else {
            CP_WAIT0();
        }
        __syncthreads();
        uint32_t sb = su + (uint32_t)(kt & 1) * STAGEB;

        #pragma unroll
        for (int ks = 0; ks < 32; ks += 16) {
            uint32_t a_h[4][4], a_l[4][4], b_h[2][4], b_l[2][4];
            #pragma unroll
            for (int mt = 0; mt < 4; mt++) {
                uint32_t off = (uint32_t)((wm + mt * 16 + (lane & 15)) * 40
                                          + ks + ((lane >> 4) << 3)) * 2;
                LDMX4(a_h[mt], sb + 0u * ABYTES + off);
                LDMX4(a_l[mt], sb + 1u * ABYTES + off);
            }
            #pragma unroll
            for (int p = 0; p < 2; p++) {
                int rb = wn + p * 16 + (lane & 7) + ((lane >> 4) << 3);
                int ce = ks + (((lane >> 3) & 1) << 3);
                uint32_t off = (uint32_t)(rb * 40 + ce) * 2;
                LDMX4(b_h[p], sb + 2u * ABYTES + off);
                LDMX4(b_l[p], sb + 3u * ABYTES + off);
            }
            #pragma unroll
            for (int mt = 0; mt < 4; mt++)
                #pragma unroll
                for (int nt = 0; nt < 4; nt++) {
                    int p = nt >> 1, q = (nt & 1) * 2;
                    mma16816(acc[mt][nt], a_h[mt], b_h[p][q], b_h[p][q + 1]);
                    mma16816(acc[mt][nt], a_h[mt], b_l[p][q], b_l[p][q + 1]);
                    mma16816(acc[mt][nt], a_l[mt], b_h[p][q], b_h[p][q + 1]);
                }
        }
        __syncthreads();
    }
}

// ---------------------------------------------------------------------------
// Fused QKV projection: grid (24, 32); n-block 0-7 -> Q, 8-15 -> K, 16-23 -> V
// Writes bf16 hi/lo head-split [B,H,S,hd]. Q pre-scaled by QSCALE.
// ---------------------------------------------------------------------------
__global__ __launch_bounds__(256) void gemm_qkv(
    const bf16* __restrict__ Ah, const bf16* __restrict__ Al,
    const bf16* __restrict__ whb, const bf16* __restrict__ wlb,
    const float* __restrict__ bq, const float* __restrict__ bk,
    const float* __restrict__ bv,
    bf16* __restrict__ qh, bf16* __restrict__ ql,
    bf16* __restrict__ kh, bf16* __restrict__ kl,
    bf16* __restrict__ vh, bf16* __restrict__ vl)
{
    extern __shared__ char smraw[];
    const uint32_t su = smem_u32(smraw);
    const int tid = threadIdx.x, lane = tid & 31, wid = tid >> 5;
    const int wsel = blockIdx.x >> 3;
    const int bn = (blockIdx.x & 7) * 128, bm = blockIdx.y * 128;
    const size_t WSZ = (size_t)D_MODEL * D_MODEL;

    const bf16* Bh = whb + (size_t)wsel * WSZ;
    const bf16* Bl = wlb + (size_t)wsel * WSZ;
    const float* bias = (wsel == 0) ? bq : (wsel == 1) ? bk : bv;
    bf16* Ch = (wsel == 0) ? qh : (wsel == 1) ? kh : vh;
    bf16* Cl = (wsel == 0) ? ql : (wsel == 1) ? kl : vl;
    const float scale = (wsel == 0) ? QSCALE : 1.0f;

    float acc[4][4][4];
    #pragma unroll
    for (int i = 0; i < 4; i++)
        #pragma unroll
        for (int j = 0; j < 4; j++)
            #pragma unroll
            for (int q = 0; q < 4; q++) acc[i][j][q] = 0.0f;

    gemm_core(su, tid, bm, bn, Ah, Al, Bh, Bl, acc);

    const int wm = (wid >> 2) * 64, wn = (wid & 3) * 32;
    #pragma unroll
    for (int mt = 0; mt < 4; mt++) {
        int m0 = bm + wm + mt * 16 + (lane >> 2);
        #pragma unroll
        for (int nt = 0; nt < 4; nt++) {
            int n = bn + wn + nt * 8 + (lane & 3) * 2;
            float bx = bias[n], by = bias[n + 1];
            float v0 = (acc[mt][nt][0] + bx) * scale;
            float v1 = (acc[mt][nt][1] + by) * scale;
            float v2 = (acc[mt][nt][2] + bx) * scale;
            float v3 = (acc[mt][nt][3] + by) * scale;
            #pragma unroll
            for (int rr = 0; rr < 2; rr++) {
                int m = m0 + rr * 8;
                float a = rr ? v2 : v0, b = rr ? v3 : v1;
                int bb = m >> 11, ss = m & 2047, hh = n >> 6, dd = n & 63;
                size_t o = (((size_t)(bb * NHEADS + hh) * SEQ + ss) * HD + dd);
                uint32_t uh = packbf(a, b);
                float2 f = unpackbf(uh);
                uint32_t ul = packbf(a - f.x, b - f.y);
                *(uint32_t*)(Ch + o) = uh;
                *(uint32_t*)(Cl + o) = ul;
            }
        }
    }
}

// ---------------------------------------------------------------------------
// Output projection: fp32 flat out
// ---------------------------------------------------------------------------
__global__ __launch_bounds__(256) void gemm_o(
    const bf16* __restrict__ Ah, const bf16* __restrict__ Al,
    const bf16* __restrict__ Bh, const bf16* __restrict__ Bl,
    const float* __restrict__ bias, float* __restrict__ Cf)
{
    extern __shared__ char smraw[];
    const uint32_t su = smem_u32(smraw);
    const int tid = threadIdx.x, lane = tid & 31, wid = tid >> 5;
    const int bn = blockIdx.x * 128, bm = blockIdx.y * 128;

    float acc[4][4][4];
    #pragma unroll
    for (int i = 0; i < 4; i++)
        #pragma unroll
        for (int j = 0; j < 4; j++)
            #pragma unroll
            for (int q = 0; q < 4; q++) acc[i][j][q] = 0.0f;

    gemm_core(su, tid, bm, bn, Ah, Al, Bh, Bl, acc);

    const int wm = (wid >> 2) * 64, wn = (wid & 3) * 32;
    #pragma unroll
    for (int mt = 0; mt < 4; mt++) {
        int m0 = bm + wm + mt * 16 + (lane >> 2);
        #pragma unroll
        for (int nt = 0; nt < 4; nt++) {
            int n = bn + wn + nt * 8 + (lane & 3) * 2;
            float bx = bias[n], by = bias[n + 1];
            *(float2*)(Cf + (size_t)m0 * D_MODEL + n) =
                make_float2(acc[mt][nt][0] + bx, acc[mt][nt][1] + by);
            *(float2*)(Cf + (size_t)(m0 + 8) * D_MODEL + n) =
                make_float2(acc[mt][nt][2] + bx, acc[mt][nt][3] + by);
        }
    }
}

// ---------------------------------------------------------------------------
// FA2 mma attention. BQ=128 (8 warps), BKV=64, split-bf16, log2-domain softmax.
// exp (MUFU) interleaved with PV mma per 16-row KV block.
// ---------------------------------------------------------------------------
#define ROWB 144u
#define Q_BYTES (128u * ROWB)
#define KV_ARR (64u * ROWB)
#define KV_STAGE (4u * KV_ARR)
#define SMEM_ATTN (2u * Q_BYTES + 2u * KV_STAGE)   // 110592

__device__ __forceinline__ void attn_issue_kv(
    uint32_t sb, const bf16* __restrict__ kh, const bf16* __restrict__ kl,
    const bf16* __restrict__ vh, const bf16* __restrict__ vl,
    size_t gbase, int j0, int tid)
{
    #pragma unroll
    for (int i = 0; i < 2; i++) {
        int c = tid + i * 256;
        int r = c >> 3, u = c & 7;
        uint32_t so = (uint32_t)r * ROWB + (uint32_t)u * 16u;
        size_t go = gbase + (size_t)(j0 + r) * HD + u * 8;
        cpa16(sb + 0u * KV_ARR + so, kh + go);
        cpa16(sb + 1u * KV_ARR + so, kl + go);
        cpa16(sb + 2u * KV_ARR + so, vh + go);
        cpa16(sb + 3u * KV_ARR + so, vl + go);
    }
    CP_COMMIT();
}

__global__ __launch_bounds__(256) void attn_mma(
    const bf16* __restrict__ qh, const bf16* __restrict__ ql,
    const bf16* __restrict__ kh, const bf16* __restrict__ kl,
    const bf16* __restrict__ vh, const bf16* __restrict__ vl,
    bf16* __restrict__ cth, bf16* __restrict__ ctl)
{
    extern __shared__ char smraw[];
    const uint32_t su = smem_u32(smraw);
    const uint32_t Qh_s = su, Ql_s = su + Q_BYTES;
    const uint32_t KV0 = su + 2u * Q_BYTES;

    const int qt = (gridDim.x - 1) - blockIdx.x;
    const int h = blockIdx.y, b = blockIdx.z;
    const int bh = b * NHEADS + h;
    const size_t gbase = (size_t)bh * SEQ * HD;
    const int q0 = qt * 128;
    const int ntiles = 2 * qt + 2;

    const int tid = threadIdx.x, lane = tid & 31, wid = tid >> 5;
    const int wm = wid * 16;
    const int qr = q0 + wm;

    #pragma unroll
    for (int i = 0; i < 4; i++) {
        int c = tid + i * 256;
        int r = c >> 3, u = c & 7;
        uint32_t so = (uint32_t)r * ROWB + (uint32_t)u * 16u;
        size_t go = gbase + (size_t)(q0 + r) * HD + u * 8;
        cpa16(Qh_s + so, qh + go);
        cpa16(Ql_s + so, ql + go);
    }
    attn_issue_kv(KV0, kh, kl, vh, vl, gbase, 0, tid);
    if (ntiles > 1) attn_issue_kv(KV0 + KV_STAGE, kh, kl, vh, vl, gbase, 64, tid);

    float o[8][4];
    #pragma unroll
    for (int nt = 0; nt < 8; nt++)
        #pragma unroll
        for (int q = 0; q < 4; q++) o[nt][q] = 0.0f;
    float m0 = -1e30f, m1 = -1e30f, l0 = 0.0f, l1 = 0.0f;

    for (int t = 0; t < ntiles; t++) {
        if (t + 1 < ntiles) CP_WAIT1(); else CP_WAIT0();
        __syncthreads();
        const int j0 = t * 64;
        const uint32_t sb = KV0 + (uint32_t)(t & 1) * KV_STAGE;
        const uint32_t kh_s = sb, kl_s = sb + KV_ARR;
        const uint32_t vh_s = sb + 2u * KV_ARR, vl_s = sb + 3u * KV_ARR;

        // ---- S = Q K^T (scores already in log2 domain via Q pre-scale) ----
        float s[8][4];
        #pragma unroll
        for (int nt = 0; nt < 8; nt++)
            #pragma unroll
            for (int q = 0; q < 4; q++) s[nt][q] = 0.0f;

        #pragma unroll
        for (int ks = 0; ks < 4; ks++) {
            uint32_t ah[4], al[4];
            {
                uint32_t off = (uint32_t)(wm + (lane & 15)) * ROWB
                             + (uint32_t)(ks * 16 + ((lane >> 4) << 3)) * 2u;
                LDMX4(ah, Qh_s + off);
                LDMX4(al, Ql_s + off);
            }
            #pragma unroll
            for (int np = 0; np < 4; np++) {
                int rk = np * 16 + ((lane >> 4) << 3) + (lane & 7);
                uint32_t off = (uint32_t)rk * ROWB
                             + (uint32_t)(ks * 16 + (((lane >> 3) & 1) << 3)) * 2u;
                uint32_t bhf[4], blf[4];
                LDMX4(bhf, kh_s + off);
                LDMX4(blf, kl_s + off);
                #pragma unroll
                for (int q2 = 0; q2 < 2; q2++) {
                    int nt = np * 2 + q2;
                    mma16816(s[nt], ah, bhf[q2 * 2], bhf[q2 * 2 + 1]);
                    mma16816(s[nt], ah, blf[q2 * 2], blf[q2 * 2 + 1]);
                    mma16816(s[nt], al, bhf[q2 * 2], bhf[q2 * 2 + 1]);
                }
            }
        }

        // ---- causal mask ----
        if (j0 + 63 > qr) {
            int r0 = qr + (lane >> 2), r1 = r0 + 8;
            #pragma unroll
            for (int nt = 0; nt < 8; nt++)
                #pragma unroll
                for (int c = 0; c < 2; c++) {
                    int k = j0 + nt * 8 + (lane & 3) * 2 + c;
                    if (k > r0) s[nt][c] = -1e30f;
                    if (k > r1) s[nt][2 + c] = -1e30f;
                }
        }

        // ---- row max + rescale of running state ----
        float mx0 = -1e30f, mx1 = -1e30f;
        #pragma unroll
        for (int nt = 0; nt < 8; nt++) {
            mx0 = fmaxf(mx0, fmaxf(s[nt][0], s[nt][1]));
            mx1 = fmaxf(mx1, fmaxf(s[nt][2], s[nt][3]));
        }
        mx0 = fmaxf(mx0, __shfl_xor_sync(0xffffffffu, mx0, 1));
        mx0 = fmaxf(mx0, __shfl_xor_sync(0xffffffffu, mx0, 2));
        mx1 = fmaxf(mx1, __shfl_xor_sync(0xffffffffu, mx1, 1));
        mx1 = fmaxf(mx1, __shfl_xor_sync(0xffffffffu, mx1, 2));
        float mn0 = fmaxf(m0, mx0), mn1 = fmaxf(m1, mx1);
        float c0 = ex2f(m0 - mn0), c1 = ex2f(m1 - mn1);
        m0 = mn0; m1 = mn1;
        #pragma unroll
        for (int nt = 0; nt < 8; nt++) {
            o[nt][0] *= c0; o[nt][1] *= c0;
            o[nt][2] *= c1; o[nt][3] *= c1;
        }
        float sum0 = 0.0f, sum1 = 0.0f;

        // ---- interleaved: exp (MUFU) + P split + PV mma per 16-row block ----
        #pragma unroll
        for (int kb = 0; kb < 4; kb++) {
            uint32_t Aph[4], Apl[4];
            #pragma unroll
            for (int half = 0; half < 2; half++) {
                int nt = kb * 2 + half;
                float p0 = ex2f(s[nt][0] - mn0);
                float p1 = ex2f(s[nt][1] - mn0);
                float p2 = ex2f(s[nt][2] - mn1);
                float p3 = ex2f(s[nt][3] - mn1);
                sum0 += p0 + p1;
                sum1 += p2 + p3;
                uint32_t u0 = packbf(p0, p1);
                float2 f0 = unpackbf(u0);
                uint32_t u1 = packbf(p2, p3);
                float2 f1 = unpackbf(u1);
                Aph[half * 2 + 0] = u0;
                Aph[half * 2 + 1] = u1;
                Apl[half * 2 + 0] = packbf(p0 - f0.x, p1 - f0.y);
                Apl[half * 2 + 1] = packbf(p2 - f1.x, p3 - f1.y);
            }
            #pragma unroll
            for (int np = 0; np < 4; np++) {
                int rv = kb * 16 + (((lane >> 3) & 1) << 3) + (lane & 7);
                int cv = np * 16 + ((lane >> 4) << 3);
                uint32_t off = (uint32_t)rv * ROWB + (uint32_t)cv * 2u;
                uint32_t vhf[4], vlf[4];
                LDMX4T(vhf, vh_s + off);
                LDMX4T(vlf, vl_s + off);
                #pragma unroll
                for (int q2 = 0; q2 < 2; q2++) {
                    int nt = np * 2 + q2;
                    mma16816(o[nt], Aph, vhf[q2 * 2], vhf[q2 * 2 + 1]);
                    mma16816(o[nt], Aph, vlf[q2 * 2], vlf[q2 * 2 + 1]);
                    mma16816(o[nt], Apl, vhf[q2 * 2], vhf[q2 * 2 + 1]);
                }
            }
        }

        sum0 += __shfl_xor_sync(0xffffffffu, sum0, 1);
        sum0 += __shfl_xor_sync(0xffffffffu, sum0, 2);
        sum1 += __shfl_xor_sync(0xffffffffu, sum1, 1);
        sum1 += __shfl_xor_sync(0xffffffffu, sum1, 2);
        l0 = l0 * c0 + sum0;
        l1 = l1 * c1 + sum1;

        __syncthreads();
        if (t + 2 < ntiles)
            attn_issue_kv(KV0 + (uint32_t)(t & 1) * KV_STAGE, kh, kl, vh, vl,
                          gbase, (t + 2) * 64, tid);
    }

    // ---- epilogue ----
    float inv0 = 1.0f / l0, inv1 = 1.0f / l1;
    int r0 = qr + (lane >> 2);
    size_t tok0 = (size_t)(b * SEQ + r0) * D_MODEL + h * HD;
    size_t tok1 = tok0 + 8 * D_MODEL;
    #pragma unroll
    for (int nt = 0; nt < 8; nt++) {
        int col = nt * 8 + (lane & 3) * 2;
        float a0 = o[nt][0] * inv0, a1 = o[nt][1] * inv0;
        uint32_t uh0 = packbf(a0, a1);
        float2 f0 = unpackbf(uh0);
        *(uint32_t*)(cth + tok0 + col) = uh0;
        *(uint32_t*)(ctl + tok0 + col) = packbf(a0 - f0.x, a1 - f0.y);
        float b0 = o[nt][2] * inv1, b1 = o[nt][3] * inv1;
        uint32_t uh1 = packbf(b0, b1);
        float2 f1 = unpackbf(uh1);
        *(uint32_t*)(cth + tok1 + col) = uh1;
        *(uint32_t*)(ctl + tok1 + col) = packbf(b0 - f1.x, b1 - f1.y);
    }
}

// ---------------------------------------------------------------------------
extern "C" void kernel_launch(void* const* d_in, const int* in_sizes, int n_in,
                              void* d_out, int out_size)
{
    const float* x  = (const float*)d_in[0];
    const float* Wq = (const float*)d_in[1];
    const float* bq = (const float*)d_in[2];
    const float* Wk = (const float*)d_in[3];
    const float* bk = (const float*)d_in[4];
    const float* Wv = (const float*)d_in[5];
    const float* bv = (const float*)d_in[6];
    const float* Wo = (const float*)d_in[7];
    const float* bo = (const float*)d_in[8];
    float* out = (float*)d_out;

    bf16 *xh, *xl, *qhp, *qlp, *khp, *klp, *vhp, *vlp, *cth, *ctl, *wh, *wl;
    cudaGetSymbolAddress((void**)&xh, g_xh);
    cudaGetSymbolAddress((void**)&xl, g_xl);
    cudaGetSymbolAddress((void**)&qhp, g_qh);
    cudaGetSymbolAddress((void**)&qlp, g_ql);
    cudaGetSymbolAddress((void**)&khp, g_kh);
    cudaGetSymbolAddress((void**)&klp, g_kl);
    cudaGetSymbolAddress((void**)&vhp, g_vh);
    cudaGetSymbolAddress((void**)&vlp, g_vl);
    cudaGetSymbolAddress((void**)&cth, g_cth);
    cudaGetSymbolAddress((void**)&ctl, g_ctl);
    cudaGetSymbolAddress((void**)&wh, g_wh);
    cudaGetSymbolAddress((void**)&wl, g_wl);

    const size_t WSZ = (size_t)D_MODEL * D_MODEL;

    split_kernel<<<1024, 256>>>(x, xh, xl, NTOK * D_MODEL);
    dim3 tg(32, 32), tb(32, 8);
    tsplit_kernel<<<tg, tb>>>(Wq, wh + 0 * WSZ, wl + 0 * WSZ);
    tsplit_kernel<<<tg, tb>>>(Wk, wh + 1 * WSZ, wl + 1 * WSZ);
    tsplit_kernel<<<tg, tb>>>(Wv, wh + 2 * WSZ, wl + 2 * WSZ);
    tsplit_kernel<<<tg, tb>>>(Wo, wh + 3 * WSZ, wl + 3 * WSZ);

    cudaFuncSetAttribute(gemm_qkv, cudaFuncAttributeMaxDynamicSharedMemorySize, SMEM_GEMM);
    cudaFuncSetAttribute(gemm_o, cudaFuncAttributeMaxDynamicSharedMemorySize, SMEM_GEMM);

    dim3 gqkv(24, NTOK / 128);   // (24, 32)
    gemm_qkv<<<gqkv, 256, SMEM_GEMM>>>(xh, xl, wh, wl, bq, bk, bv,
                                       qhp, qlp, khp, klp, vhp, vlp);

    cudaFuncSetAttribute(attn_mma, cudaFuncAttributeMaxDynamicSharedMemorySize, SMEM_ATTN);
    dim3 ga(SEQ / 128, NHEADS, BATCH);
    attn_mma<<<ga, 256, SMEM_ATTN>>>(qhp, qlp, khp, klp, vhp, vlp, cth, ctl);

    gemm_o<<<dim3(D_MODEL / 128, NTOK / 128), 256, SMEM_GEMM>>>(
        cth, ctl, wh + 3 * WSZ, wl + 3 * WSZ, bo, out);
}

// round 9
// speedup vs baseline: 3.4816x; 1.2858x over previous
#include <cuda_runtime.h>
#include <cuda_bf16.h>
#include <cuda_fp16.h>
#include <cstdint>
#include <math.h>

#define D_MODEL 1024
#define NHEADS 16
#define HD 64
#define BATCH 2
#define SEQ 2048
#define NTOK (BATCH * SEQ)   // 4096

// Q pre-scale: (1/sqrt(64)) * log2(e)  -> scores in log2 domain
#define QSCALE 0.180336875967866f

typedef __nv_bfloat16 bf16;

// ---------------------------------------------------------------------------
// Scratch (no allocations allowed)
// ---------------------------------------------------------------------------
__device__ bf16 g_xh[(size_t)NTOK * D_MODEL];
__device__ bf16 g_xl[(size_t)NTOK * D_MODEL];
__device__ __half g_q16[(size_t)NTOK * D_MODEL];   // [B,H,S,hd] fp16, scaled
__device__ __half g_k16[(size_t)NTOK * D_MODEL];
__device__ __half g_v16[(size_t)NTOK * D_MODEL];
__device__ bf16 g_cth[(size_t)NTOK * D_MODEL];
__device__ bf16 g_ctl[(size_t)NTOK * D_MODEL];
__device__ bf16 g_wh[(size_t)4 * D_MODEL * D_MODEL];  // [n][k] transposed
__device__ bf16 g_wl[(size_t)4 * D_MODEL * D_MODEL];

// ---------------------------------------------------------------------------
// Helpers (generic sm_80+ PTX only)
// ---------------------------------------------------------------------------
__device__ __forceinline__ uint32_t smem_u32(const void* p) {
    uint32_t a;
    asm("{ .reg .u64 t; cvta.to.shared.u64 t, %1; cvt.u32.u64 %0, t; }" : "=r"(a) : "l"(p));
    return a;
}
__device__ __forceinline__ void cpa16(uint32_t s, const void* g) {
    asm volatile("cp.async.cg.shared.global [%0], [%1], 16;" :: "r"(s), "l"(g));
}
#define CP_COMMIT() asm volatile("cp.async.commit_group;" ::: "memory")
#define CP_WAIT1()  asm volatile("cp.async.wait_group 1;" ::: "memory")
#define CP_WAIT0()  asm volatile("cp.async.wait_group 0;" ::: "memory")

#define LDMX4(r, a) \
    asm volatile("ldmatrix.sync.aligned.m8n8.x4.shared.b16 {%0,%1,%2,%3}, [%4];" \
        : "=r"((r)[0]), "=r"((r)[1]), "=r"((r)[2]), "=r"((r)[3]) : "r"(a))
#define LDMX4T(r, a) \
    asm volatile("ldmatrix.sync.aligned.m8n8.x4.trans.shared.b16 {%0,%1,%2,%3}, [%4];" \
        : "=r"((r)[0]), "=r"((r)[1]), "=r"((r)[2]), "=r"((r)[3]) : "r"(a))

__device__ __forceinline__ void mma16816(float* c, const uint32_t* a, uint32_t b0, uint32_t b1) {
    asm volatile(
        "mma.sync.aligned.m16n8k16.row.col.f32.bf16.bf16.f32 "
        "{%0,%1,%2,%3}, {%4,%5,%6,%7}, {%8,%9}, {%0,%1,%2,%3};"
        : "+f"(c[0]), "+f"(c[1]), "+f"(c[2]), "+f"(c[3])
        : "r"(a[0]), "r"(a[1]), "r"(a[2]), "r"(a[3]), "r"(b0), "r"(b1));
}
__device__ __forceinline__ void mma16816h(float* c, const uint32_t* a, uint32_t b0, uint32_t b1) {
    asm volatile(
        "mma.sync.aligned.m16n8k16.row.col.f32.f16.f16.f32 "
        "{%0,%1,%2,%3}, {%4,%5,%6,%7}, {%8,%9}, {%0,%1,%2,%3};"
        : "+f"(c[0]), "+f"(c[1]), "+f"(c[2]), "+f"(c[3])
        : "r"(a[0]), "r"(a[1]), "r"(a[2]), "r"(a[3]), "r"(b0), "r"(b1));
}

__device__ __forceinline__ uint32_t packbf(float lo, float hi) {
    uint32_t r;
    asm("cvt.rn.bf16x2.f32 %0, %1, %2;" : "=r"(r) : "f"(hi), "f"(lo));
    return r;
}
__device__ __forceinline__ uint32_t packh(float lo, float hi) {
    uint32_t r;
    asm("cvt.rn.f16x2.f32 %0, %1, %2;" : "=r"(r) : "f"(hi), "f"(lo));
    return r;
}
__device__ __forceinline__ float2 unpackbf(uint32_t u) {
    __nv_bfloat162 b = *(__nv_bfloat162*)&u;
    return make_float2(__bfloat162float(b.x), __bfloat162float(b.y));
}
__device__ __forceinline__ float ex2f(float x) {
    float y;
    asm("ex2.approx.f32 %0, %1;" : "=f"(y) : "f"(x));
    return y;
}

// ---------------------------------------------------------------------------
// Conversion kernels
// ---------------------------------------------------------------------------
__global__ void split_kernel(const float* __restrict__ s, bf16* __restrict__ h,
                             bf16* __restrict__ l, int n) {
    int i = blockIdx.x * blockDim.x + threadIdx.x;
    int stride = gridDim.x * blockDim.x;
    for (; i < n; i += stride) {
        float v = s[i];
        bf16 hi = __float2bfloat16(v);
        h[i] = hi;
        l[i] = __float2bfloat16(v - __bfloat162float(hi));
    }
}

// Fused: 4 weights [k][n] fp32 -> hi/lo [n][k] bf16; blockIdx.z selects weight
__global__ void tsplit4_kernel(const float* __restrict__ W0, const float* __restrict__ W1,
                               const float* __restrict__ W2, const float* __restrict__ W3,
                               bf16* __restrict__ th, bf16* __restrict__ tl) {
    __shared__ float t[32][33];
    const int z = blockIdx.z;
    const float* W = (z == 0) ? W0 : (z == 1) ? W1 : (z == 2) ? W2 : W3;
    const size_t WSZ = (size_t)D_MODEL * D_MODEL;
    bf16* thz = th + z * WSZ;
    bf16* tlz = tl + z * WSZ;
    int n0 = blockIdx.x * 32, k0 = blockIdx.y * 32;
    int x = threadIdx.x, y = threadIdx.y;  // 32x8
    #pragma unroll
    for (int j = 0; j < 32; j += 8)
        t[y + j][x] = W[(size_t)(k0 + y + j) * D_MODEL + n0 + x];
    __syncthreads();
    #pragma unroll
    for (int j = 0; j < 32; j += 8) {
        float v = t[x][y + j];
        bf16 hi = __float2bfloat16(v);
        size_t o = (size_t)(n0 + y + j) * D_MODEL + k0 + x;
        thz[o] = hi;
        tlz[o] = __float2bfloat16(v - __bfloat162float(hi));
    }
}

// ---------------------------------------------------------------------------
// Shared GEMM mainloop (3-term split-bf16, full precision)
// ---------------------------------------------------------------------------
#define ABYTES 10240u
#define STAGEB (4u * ABYTES)
#define SMEM_GEMM (2u * STAGEB)

__device__ __forceinline__ void issue_stage(
    uint32_t su, int stage, int k0, int tid, int bm, int bn,
    const bf16* __restrict__ Ah, const bf16* __restrict__ Al,
    const bf16* __restrict__ Bh, const bf16* __restrict__ Bl)
{
    uint32_t sb = su + (uint32_t)stage * STAGEB;
    #pragma unroll
    for (int j = 0; j < 2; j++) {
        int idx = tid + j * 256;
        int r = idx >> 2, c8 = idx & 3;
        uint32_t so = (uint32_t)(r * 40 + c8 * 8) * 2;
        size_t goA = (size_t)(bm + r) * D_MODEL + k0 + c8 * 8;
        size_t goB = (size_t)(bn + r) * D_MODEL + k0 + c8 * 8;
        cpa16(sb + 0u * ABYTES + so, Ah + goA);
        cpa16(sb + 1u * ABYTES + so, Al + goA);
        cpa16(sb + 2u * ABYTES + so, Bh + goB);
        cpa16(sb + 3u * ABYTES + so, Bl + goB);
    }
    CP_COMMIT();
}

__device__ __forceinline__ void gemm_core(
    uint32_t su, int tid, int bm, int bn,
    const bf16* __restrict__ Ah, const bf16* __restrict__ Al,
    const bf16* __restrict__ Bh, const bf16* __restrict__ Bl,
    float acc[4][4][4])
{
    const int lane = tid & 31, wid = tid >> 5;
    const int wm = (wid >> 2) * 64, wn = (wid & 3) * 32;

    issue_stage(su, 0, 0, tid, bm, bn, Ah, Al, Bh, Bl);

    const int NKT = D_MODEL / 32;
    for (int kt = 0; kt < NKT; kt++) {
        if (kt + 1 < NKT) {
            issue_stage(su, (kt + 1) & 1, (kt + 1) * 32, tid, bm, bn, Ah, Al, Bh, Bl);
            CP_WAIT1();
        } else {
            CP_WAIT0();
        }
        __syncthreads();
        uint32_t sb = su + (uint32_t)(kt & 1) * STAGEB;

        #pragma unroll
        for (int ks = 0; ks < 32; ks += 16) {
            uint32_t a_h[4][4], a_l[4][4], b_h[2][4], b_l[2][4];
            #pragma unroll
            for (int mt = 0; mt < 4; mt++) {
                uint32_t off = (uint32_t)((wm + mt * 16 + (lane & 15)) * 40
                                          + ks + ((lane >> 4) << 3)) * 2;
                LDMX4(a_h[mt], sb + 0u * ABYTES + off);
                LDMX4(a_l[mt], sb + 1u * ABYTES + off);
            }
            #pragma unroll
            for (int p = 0; p < 2; p++) {
                int rb = wn + p * 16 + (lane & 7) + ((lane >> 4) << 3);
                int ce = ks + (((lane >> 3) & 1) << 3);
                uint32_t off = (uint32_t)(rb * 40 + ce) * 2;
                LDMX4(b_h[p], sb + 2u * ABYTES + off);
                LDMX4(b_l[p], sb + 3u * ABYTES + off);
            }
            #pragma unroll
            for (int mt = 0; mt < 4; mt++)
                #pragma unroll
                for (int nt = 0; nt < 4; nt++) {
                    int p = nt >> 1, q = (nt & 1) * 2;
                    mma16816(acc[mt][nt], a_h[mt], b_h[p][q], b_h[p][q + 1]);
                    mma16816(acc[mt][nt], a_h[mt], b_l[p][q], b_l[p][q + 1]);
                    mma16816(acc[mt][nt], a_l[mt], b_h[p][q], b_h[p][q + 1]);
                }
        }
        __syncthreads();
    }
}

// ---------------------------------------------------------------------------
// Fused QKV projection: outputs fp16 (single array each), Q pre-scaled.
// ---------------------------------------------------------------------------
__global__ __launch_bounds__(256) void gemm_qkv(
    const bf16* __restrict__ Ah, const bf16* __restrict__ Al,
    const bf16* __restrict__ whb, const bf16* __restrict__ wlb,
    const float* __restrict__ bq, const float* __restrict__ bk,
    const float* __restrict__ bv,
    __half* __restrict__ q16, __half* __restrict__ k16, __half* __restrict__ v16)
{
    extern __shared__ char smraw[];
    const uint32_t su = smem_u32(smraw);
    const int tid = threadIdx.x, lane = tid & 31, wid = tid >> 5;
    const int wsel = blockIdx.x >> 3;
    const int bn = (blockIdx.x & 7) * 128, bm = blockIdx.y * 128;
    const size_t WSZ = (size_t)D_MODEL * D_MODEL;

    const bf16* Bh = whb + (size_t)wsel * WSZ;
    const bf16* Bl = wlb + (size_t)wsel * WSZ;
    const float* bias = (wsel == 0) ? bq : (wsel == 1) ? bk : bv;
    __half* C = (wsel == 0) ? q16 : (wsel == 1) ? k16 : v16;
    const float scale = (wsel == 0) ? QSCALE : 1.0f;

    float acc[4][4][4];
    #pragma unroll
    for (int i = 0; i < 4; i++)
        #pragma unroll
        for (int j = 0; j < 4; j++)
            #pragma unroll
            for (int q = 0; q < 4; q++) acc[i][j][q] = 0.0f;

    gemm_core(su, tid, bm, bn, Ah, Al, Bh, Bl, acc);

    const int wm = (wid >> 2) * 64, wn = (wid & 3) * 32;
    #pragma unroll
    for (int mt = 0; mt < 4; mt++) {
        int m0 = bm + wm + mt * 16 + (lane >> 2);
        #pragma unroll
        for (int nt = 0; nt < 4; nt++) {
            int n = bn + wn + nt * 8 + (lane & 3) * 2;
            float bx = bias[n], by = bias[n + 1];
            float v0 = (acc[mt][nt][0] + bx) * scale;
            float v1 = (acc[mt][nt][1] + by) * scale;
            float v2 = (acc[mt][nt][2] + bx) * scale;
            float v3 = (acc[mt][nt][3] + by) * scale;
            #pragma unroll
            for (int rr = 0; rr < 2; rr++) {
                int m = m0 + rr * 8;
                float a = rr ? v2 : v0, b = rr ? v3 : v1;
                int bb = m >> 11, ss = m & 2047, hh = n >> 6, dd = n & 63;
                size_t o = (((size_t)(bb * NHEADS + hh) * SEQ + ss) * HD + dd);
                *(uint32_t*)(C + o) = packh(a, b);
            }
        }
    }
}

// ---------------------------------------------------------------------------
// Output projection: fp32 flat out
// ---------------------------------------------------------------------------
__global__ __launch_bounds__(256) void gemm_o(
    const bf16* __restrict__ Ah, const bf16* __restrict__ Al,
    const bf16* __restrict__ Bh, const bf16* __restrict__ Bl,
    const float* __restrict__ bias, float* __restrict__ Cf)
{
    extern __shared__ char smraw[];
    const uint32_t su = smem_u32(smraw);
    const int tid = threadIdx.x, lane = tid & 31, wid = tid >> 5;
    const int bn = blockIdx.x * 128, bm = blockIdx.y * 128;

    float acc[4][4][4];
    #pragma unroll
    for (int i = 0; i < 4; i++)
        #pragma unroll
        for (int j = 0; j < 4; j++)
            #pragma unroll
            for (int q = 0; q < 4; q++) acc[i][j][q] = 0.0f;

    gemm_core(su, tid, bm, bn, Ah, Al, Bh, Bl, acc);

    const int wm = (wid >> 2) * 64, wn = (wid & 3) * 32;
    #pragma unroll
    for (int mt = 0; mt < 4; mt++) {
        int m0 = bm + wm + mt * 16 + (lane >> 2);
        #pragma unroll
        for (int nt = 0; nt < 4; nt++) {
            int n = bn + wn + nt * 8 + (lane & 3) * 2;
            float bx = bias[n], by = bias[n + 1];
            *(float2*)(Cf + (size_t)m0 * D_MODEL + n) =
                make_float2(acc[mt][nt][0] + bx, acc[mt][nt][1] + by);
            *(float2*)(Cf + (size_t)(m0 + 8) * D_MODEL + n) =
                make_float2(acc[mt][nt][2] + bx, acc[mt][nt][3] + by);
        }
    }
}

// ---------------------------------------------------------------------------
// FA2 mma attention, plain fp16 operands (fp32 accum). BQ=128, BKV=64.
// fp16 quantization (2^-11) keeps calibrated error ~4e-4 total.
// ---------------------------------------------------------------------------
#define ROWB 144u
#define Q_BYTES (128u * ROWB)                    // 18432, single fp16 array
#define KV_ARR (64u * ROWB)                      // 9216
#define KV_STAGE (2u * KV_ARR)                   // K, V
#define SMEM_ATTN (Q_BYTES + 2u * KV_STAGE)      // 55296

__device__ __forceinline__ void attn_issue_kv(
    uint32_t sb, const __half* __restrict__ k16, const __half* __restrict__ v16,
    size_t gbase, int j0, int tid)
{
    #pragma unroll
    for (int i = 0; i < 2; i++) {
        int c = tid + i * 256;
        int r = c >> 3, u = c & 7;
        uint32_t so = (uint32_t)r * ROWB + (uint32_t)u * 16u;
        size_t go = gbase + (size_t)(j0 + r) * HD + u * 8;
        cpa16(sb + 0u * KV_ARR + so, k16 + go);
        cpa16(sb + 1u * KV_ARR + so, v16 + go);
    }
    CP_COMMIT();
}

__global__ __launch_bounds__(256) void attn_mma(
    const __half* __restrict__ q16, const __half* __restrict__ k16,
    const __half* __restrict__ v16,
    bf16* __restrict__ cth, bf16* __restrict__ ctl)
{
    extern __shared__ char smraw[];
    const uint32_t su = smem_u32(smraw);
    const uint32_t Q_s = su;
    const uint32_t KV0 = su + Q_BYTES;

    const int qt = (gridDim.x - 1) - blockIdx.x;
    const int h = blockIdx.y, b = blockIdx.z;
    const int bh = b * NHEADS + h;
    const size_t gbase = (size_t)bh * SEQ * HD;
    const int q0 = qt * 128;
    const int ntiles = 2 * qt + 2;

    const int tid = threadIdx.x, lane = tid & 31, wid = tid >> 5;
    const int wm = wid * 16;
    const int qr = q0 + wm;

    #pragma unroll
    for (int i = 0; i < 4; i++) {
        int c = tid + i * 256;
        int r = c >> 3, u = c & 7;
        uint32_t so = (uint32_t)r * ROWB + (uint32_t)u * 16u;
        cpa16(Q_s + so, q16 + gbase + (size_t)(q0 + r) * HD + u * 8);
    }
    attn_issue_kv(KV0, k16, v16, gbase, 0, tid);
    if (ntiles > 1) attn_issue_kv(KV0 + KV_STAGE, k16, v16, gbase, 64, tid);

    float o[8][4];
    #pragma unroll
    for (int nt = 0; nt < 8; nt++)
        #pragma unroll
        for (int q = 0; q < 4; q++) o[nt][q] = 0.0f;
    float m0 = -1e30f, m1 = -1e30f, l0 = 0.0f, l1 = 0.0f;

    for (int t = 0; t < ntiles; t++) {
        if (t + 1 < ntiles) CP_WAIT1(); else CP_WAIT0();
        __syncthreads();
        const int j0 = t * 64;
        const uint32_t sb = KV0 + (uint32_t)(t & 1) * KV_STAGE;
        const uint32_t k_s = sb, v_s = sb + KV_ARR;

        // ---- S = Q K^T (log2 domain) ----
        float s[8][4];
        #pragma unroll
        for (int nt = 0; nt < 8; nt++)
            #pragma unroll
            for (int q = 0; q < 4; q++) s[nt][q] = 0.0f;

        #pragma unroll
        for (int ks = 0; ks < 4; ks++) {
            uint32_t ah[4];
            {
                uint32_t off = (uint32_t)(wm + (lane & 15)) * ROWB
                             + (uint32_t)(ks * 16 + ((lane >> 4) << 3)) * 2u;
                LDMX4(ah, Q_s + off);
            }
            #pragma unroll
            for (int np = 0; np < 4; np++) {
                int rk = np * 16 + ((lane >> 4) << 3) + (lane & 7);
                uint32_t off = (uint32_t)rk * ROWB
                             + (uint32_t)(ks * 16 + (((lane >> 3) & 1) << 3)) * 2u;
                uint32_t kf[4];
                LDMX4(kf, k_s + off);
                #pragma unroll
                for (int q2 = 0; q2 < 2; q2++)
                    mma16816h(s[np * 2 + q2], ah, kf[q2 * 2], kf[q2 * 2 + 1]);
            }
        }

        // ---- causal mask ----
        if (j0 + 63 > qr) {
            int r0 = qr + (lane >> 2), r1 = r0 + 8;
            #pragma unroll
            for (int nt = 0; nt < 8; nt++)
                #pragma unroll
                for (int c = 0; c < 2; c++) {
                    int k = j0 + nt * 8 + (lane & 3) * 2 + c;
                    if (k > r0) s[nt][c] = -1e30f;
                    if (k > r1) s[nt][2 + c] = -1e30f;
                }
        }

        // ---- row max + rescale running state ----
        float mx0 = -1e30f, mx1 = -1e30f;
        #pragma unroll
        for (int nt = 0; nt < 8; nt++) {
            mx0 = fmaxf(mx0, fmaxf(s[nt][0], s[nt][1]));
            mx1 = fmaxf(mx1, fmaxf(s[nt][2], s[nt][3]));
        }
        mx0 = fmaxf(mx0, __shfl_xor_sync(0xffffffffu, mx0, 1));
        mx0 = fmaxf(mx0, __shfl_xor_sync(0xffffffffu, mx0, 2));
        mx1 = fmaxf(mx1, __shfl_xor_sync(0xffffffffu, mx1, 1));
        mx1 = fmaxf(mx1, __shfl_xor_sync(0xffffffffu, mx1, 2));
        float mn0 = fmaxf(m0, mx0), mn1 = fmaxf(m1, mx1);
        float c0 = ex2f(m0 - mn0), c1 = ex2f(m1 - mn1);
        m0 = mn0; m1 = mn1;
        #pragma unroll
        for (int nt = 0; nt < 8; nt++) {
            o[nt][0] *= c0; o[nt][1] *= c0;
            o[nt][2] *= c1; o[nt][3] *= c1;
        }
        float sum0 = 0.0f, sum1 = 0.0f;

        // ---- interleaved exp + P pack (fp16) + PV mma ----
        #pragma unroll
        for (int kb = 0; kb < 4; kb++) {
            uint32_t Ap[4];
            #pragma unroll
            for (int half = 0; half < 2; half++) {
                int nt = kb * 2 + half;
                float p0 = ex2f(s[nt][0] - mn0);
                float p1 = ex2f(s[nt][1] - mn0);
                float p2 = ex2f(s[nt][2] - mn1);
                float p3 = ex2f(s[nt][3] - mn1);
                sum0 += p0 + p1;
                sum1 += p2 + p3;
                Ap[half * 2 + 0] = packh(p0, p1);
                Ap[half * 2 + 1] = packh(p2, p3);
            }
            #pragma unroll
            for (int np = 0; np < 4; np++) {
                int rv = kb * 16 + (((lane >> 3) & 1) << 3) + (lane & 7);
                int cv = np * 16 + ((lane >> 4) << 3);
                uint32_t off = (uint32_t)rv * ROWB + (uint32_t)cv * 2u;
                uint32_t vf[4];
                LDMX4T(vf, v_s + off);
                #pragma unroll
                for (int q2 = 0; q2 < 2; q2++)
                    mma16816h(o[np * 2 + q2], Ap, vf[q2 * 2], vf[q2 * 2 + 1]);
            }
        }

        sum0 += __shfl_xor_sync(0xffffffffu, sum0, 1);
        sum0 += __shfl_xor_sync(0xffffffffu, sum0, 2);
        sum1 += __shfl_xor_sync(0xffffffffu, sum1, 1);
        sum1 += __shfl_xor_sync(0xffffffffu, sum1, 2);
        l0 = l0 * c0 + sum0;
        l1 = l1 * c1 + sum1;

        __syncthreads();
        if (t + 2 < ntiles)
            attn_issue_kv(KV0 + (uint32_t)(t & 1) * KV_STAGE, k16, v16,
                          gbase, (t + 2) * 64, tid);
    }

    // ---- epilogue: normalize, split bf16 hi/lo ctx ----
    float inv0 = 1.0f / l0, inv1 = 1.0f / l1;
    int r0 = qr + (lane >> 2);
    size_t tok0 = (size_t)(b * SEQ + r0) * D_MODEL + h * HD;
    size_t tok1 = tok0 + 8 * D_MODEL;
    #pragma unroll
    for (int nt = 0; nt < 8; nt++) {
        int col = nt * 8 + (lane & 3) * 2;
        float a0 = o[nt][0] * inv0, a1 = o[nt][1] * inv0;
        uint32_t uh0 = packbf(a0, a1);
        float2 f0 = unpackbf(uh0);
        *(uint32_t*)(cth + tok0 + col) = uh0;
        *(uint32_t*)(ctl + tok0 + col) = packbf(a0 - f0.x, a1 - f0.y);
        float b0 = o[nt][2] * inv1, b1 = o[nt][3] * inv1;
        uint32_t uh1 = packbf(b0, b1);
        float2 f1 = unpackbf(uh1);
        *(uint32_t*)(cth + tok1 + col) = uh1;
        *(uint32_t*)(ctl + tok1 + col) = packbf(b0 - f1.x, b1 - f1.y);
    }
}

// ---------------------------------------------------------------------------
extern "C" void kernel_launch(void* const* d_in, const int* in_sizes, int n_in,
                              void* d_out, int out_size)
{
    const float* x  = (const float*)d_in[0];
    const float* Wq = (const float*)d_in[1];
    const float* bq = (const float*)d_in[2];
    const float* Wk = (const float*)d_in[3];
    const float* bk = (const float*)d_in[4];
    const float* Wv = (const float*)d_in[5];
    const float* bv = (const float*)d_in[6];
    const float* Wo = (const float*)d_in[7];
    const float* bo = (const float*)d_in[8];
    float* out = (float*)d_out;

    bf16 *xh, *xl, *cth, *ctl, *wh, *wl;
    __half *qp, *kp, *vp;
    cudaGetSymbolAddress((void**)&xh, g_xh);
    cudaGetSymbolAddress((void**)&xl, g_xl);
    cudaGetSymbolAddress((void**)&qp, g_q16);
    cudaGetSymbolAddress((void**)&kp, g_k16);
    cudaGetSymbolAddress((void**)&vp, g_v16);
    cudaGetSymbolAddress((void**)&cth, g_cth);
    cudaGetSymbolAddress((void**)&ctl, g_ctl);
    cudaGetSymbolAddress((void**)&wh, g_wh);
    cudaGetSymbolAddress((void**)&wl, g_wl);

    const size_t WSZ = (size_t)D_MODEL * D_MODEL;

    split_kernel<<<1024, 256>>>(x, xh, xl, NTOK * D_MODEL);
    dim3 tg(32, 32, 4), tb(32, 8);
    tsplit4_kernel<<<tg, tb>>>(Wq, Wk, Wv, Wo, wh, wl);

    cudaFuncSetAttribute(gemm_qkv, cudaFuncAttributeMaxDynamicSharedMemorySize, SMEM_GEMM);
    cudaFuncSetAttribute(gemm_o, cudaFuncAttributeMaxDynamicSharedMemorySize, SMEM_GEMM);

    dim3 gqkv(24, NTOK / 128);
    gemm_qkv<<<gqkv, 256, SMEM_GEMM>>>(xh, xl, wh, wl, bq, bk, bv, qp, kp, vp);

    cudaFuncSetAttribute(attn_mma, cudaFuncAttributeMaxDynamicSharedMemorySize, SMEM_ATTN);
    dim3 ga(SEQ / 128, NHEADS, BATCH);
    attn_mma<<<ga, 256, SMEM_ATTN>>>(qp, kp, vp, cth, ctl);

    gemm_o<<<dim3(D_MODEL / 128, NTOK / 128), 256, SMEM_GEMM>>>(
        cth, ctl, wh + 3 * WSZ, wl + 3 * WSZ, bo, out);
}

// round 10
// speedup vs baseline: 4.1025x; 1.1783x over previous
#include <cuda_runtime.h>
#include <cuda_bf16.h>
#include <cuda_fp16.h>
#include <cstdint>
#include <math.h>

#define D_MODEL 1024
#define NHEADS 16
#define HD 64
#define BATCH 2
#define SEQ 2048
#define NTOK (BATCH * SEQ)   // 4096

// Q pre-scale: (1/sqrt(64)) * log2(e)  -> scores in log2 domain
#define QSCALE 0.180336875967866f

typedef __nv_bfloat16 bf16;

// ---------------------------------------------------------------------------
// Scratch (no allocations allowed)
// ---------------------------------------------------------------------------
__device__ __half g_xh16[(size_t)NTOK * D_MODEL];    // x fp16 hi
__device__ __half g_xl16[(size_t)NTOK * D_MODEL];    // x fp16 lo
__device__ __half g_q16[(size_t)NTOK * D_MODEL];     // [B,H,S,hd] fp16, scaled
__device__ __half g_k16[(size_t)NTOK * D_MODEL];
__device__ __half g_v16[(size_t)NTOK * D_MODEL];
__device__ __half g_cth16[(size_t)NTOK * D_MODEL];   // ctx fp16 hi
__device__ __half g_ctl16[(size_t)NTOK * D_MODEL];   // ctx fp16 lo
__device__ __half g_w16[(size_t)4 * D_MODEL * D_MODEL];  // [n][k] transposed fp16

// ---------------------------------------------------------------------------
// Helpers (generic sm_80+ PTX only)
// ---------------------------------------------------------------------------
__device__ __forceinline__ uint32_t smem_u32(const void* p) {
    uint32_t a;
    asm("{ .reg .u64 t; cvta.to.shared.u64 t, %1; cvt.u32.u64 %0, t; }" : "=r"(a) : "l"(p));
    return a;
}
__device__ __forceinline__ void cpa16(uint32_t s, const void* g) {
    asm volatile("cp.async.cg.shared.global [%0], [%1], 16;" :: "r"(s), "l"(g));
}
#define CP_COMMIT() asm volatile("cp.async.commit_group;" ::: "memory")
#define CP_WAIT1()  asm volatile("cp.async.wait_group 1;" ::: "memory")
#define CP_WAIT0()  asm volatile("cp.async.wait_group 0;" ::: "memory")

#define LDMX4(r, a) \
    asm volatile("ldmatrix.sync.aligned.m8n8.x4.shared.b16 {%0,%1,%2,%3}, [%4];" \
        : "=r"((r)[0]), "=r"((r)[1]), "=r"((r)[2]), "=r"((r)[3]) : "r"(a))
#define LDMX4T(r, a) \
    asm volatile("ldmatrix.sync.aligned.m8n8.x4.trans.shared.b16 {%0,%1,%2,%3}, [%4];" \
        : "=r"((r)[0]), "=r"((r)[1]), "=r"((r)[2]), "=r"((r)[3]) : "r"(a))

__device__ __forceinline__ void mma16816h(float* c, const uint32_t* a, uint32_t b0, uint32_t b1) {
    asm volatile(
        "mma.sync.aligned.m16n8k16.row.col.f32.f16.f16.f32 "
        "{%0,%1,%2,%3}, {%4,%5,%6,%7}, {%8,%9}, {%0,%1,%2,%3};"
        : "+f"(c[0]), "+f"(c[1]), "+f"(c[2]), "+f"(c[3])
        : "r"(a[0]), "r"(a[1]), "r"(a[2]), "r"(a[3]), "r"(b0), "r"(b1));
}

__device__ __forceinline__ uint32_t packh(float lo, float hi) {
    uint32_t r;
    asm("cvt.rn.f16x2.f32 %0, %1, %2;" : "=r"(r) : "f"(hi), "f"(lo));
    return r;
}
__device__ __forceinline__ float2 unpackh(uint32_t u) {
    __half2 h = *(__half2*)&u;
    return make_float2(__half2float(h.x), __half2float(h.y));
}
__device__ __forceinline__ float ex2f(float x) {
    float y;
    asm("ex2.approx.f32 %0, %1;" : "=f"(y) : "f"(x));
    return y;
}

// ---------------------------------------------------------------------------
// Conversion kernels
// ---------------------------------------------------------------------------
__global__ void splith_kernel(const float* __restrict__ s, __half* __restrict__ h,
                              __half* __restrict__ l, int n) {
    int i = blockIdx.x * blockDim.x + threadIdx.x;
    int stride = gridDim.x * blockDim.x;
    for (; i < n; i += stride) {
        float v = s[i];
        __half hi = __float2half(v);
        h[i] = hi;
        l[i] = __float2half(v - __half2float(hi));
    }
}

// Fused: 4 weights [k][n] fp32 -> single fp16 [n][k]; blockIdx.z selects weight
__global__ void tsplit4_kernel(const float* __restrict__ W0, const float* __restrict__ W1,
                               const float* __restrict__ W2, const float* __restrict__ W3,
                               __half* __restrict__ t16) {
    __shared__ float t[32][33];
    const int z = blockIdx.z;
    const float* W = (z == 0) ? W0 : (z == 1) ? W1 : (z == 2) ? W2 : W3;
    const size_t WSZ = (size_t)D_MODEL * D_MODEL;
    __half* tz = t16 + z * WSZ;
    int n0 = blockIdx.x * 32, k0 = blockIdx.y * 32;
    int x = threadIdx.x, y = threadIdx.y;  // 32x8
    #pragma unroll
    for (int j = 0; j < 32; j += 8)
        t[y + j][x] = W[(size_t)(k0 + y + j) * D_MODEL + n0 + x];
    __syncthreads();
    #pragma unroll
    for (int j = 0; j < 32; j += 8)
        tz[(size_t)(n0 + y + j) * D_MODEL + k0 + x] = __float2half(t[x][y + j]);
}

// ---------------------------------------------------------------------------
// Shared GEMM mainloop: 2-term split-fp16 A, single fp16 B
// D = (Ah + Al) @ B^T   (A residual exact to 2^-22; B fp16-quantized)
// ---------------------------------------------------------------------------
#define ABYTES 10240u
#define STAGEB (3u * ABYTES)       // Ah, Al, B
#define SMEM_GEMM (2u * STAGEB)    // 61440

__device__ __forceinline__ void issue_stage(
    uint32_t su, int stage, int k0, int tid, int bm, int bn,
    const __half* __restrict__ Ah, const __half* __restrict__ Al,
    const __half* __restrict__ Bh)
{
    uint32_t sb = su + (uint32_t)stage * STAGEB;
    #pragma unroll
    for (int j = 0; j < 2; j++) {
        int idx = tid + j * 256;
        int r = idx >> 2, c8 = idx & 3;
        uint32_t so = (uint32_t)(r * 40 + c8 * 8) * 2;
        size_t goA = (size_t)(bm + r) * D_MODEL + k0 + c8 * 8;
        size_t goB = (size_t)(bn + r) * D_MODEL + k0 + c8 * 8;
        cpa16(sb + 0u * ABYTES + so, Ah + goA);
        cpa16(sb + 1u * ABYTES + so, Al + goA);
        cpa16(sb + 2u * ABYTES + so, Bh + goB);
    }
    CP_COMMIT();
}

__device__ __forceinline__ void gemm_core(
    uint32_t su, int tid, int bm, int bn,
    const __half* __restrict__ Ah, const __half* __restrict__ Al,
    const __half* __restrict__ Bh,
    float acc[4][4][4])
{
    const int lane = tid & 31, wid = tid >> 5;
    const int wm = (wid >> 2) * 64, wn = (wid & 3) * 32;

    issue_stage(su, 0, 0, tid, bm, bn, Ah, Al, Bh);

    const int NKT = D_MODEL / 32;
    for (int kt = 0; kt < NKT; kt++) {
        if (kt + 1 < NKT) {
            issue_stage(su, (kt + 1) & 1, (kt + 1) * 32, tid, bm, bn, Ah, Al, Bh);
            CP_WAIT1();
        } else {
            CP_WAIT0();
        }
        __syncthreads();
        uint32_t sb = su + (uint32_t)(kt & 1) * STAGEB;

        #pragma unroll
        for (int ks = 0; ks < 32; ks += 16) {
            uint32_t a_h[4][4], a_l[4][4], b_f[2][4];
            #pragma unroll
            for (int mt = 0; mt < 4; mt++) {
                uint32_t off = (uint32_t)((wm + mt * 16 + (lane & 15)) * 40
                                          + ks + ((lane >> 4) << 3)) * 2;
                LDMX4(a_h[mt], sb + 0u * ABYTES + off);
                LDMX4(a_l[mt], sb + 1u * ABYTES + off);
            }
            #pragma unroll
            for (int p = 0; p < 2; p++) {
                int rb = wn + p * 16 + (lane & 7) + ((lane >> 4) << 3);
                int ce = ks + (((lane >> 3) & 1) << 3);
                uint32_t off = (uint32_t)(rb * 40 + ce) * 2;
                LDMX4(b_f[p], sb + 2u * ABYTES + off);
            }
            #pragma unroll
            for (int mt = 0; mt < 4; mt++)
                #pragma unroll
                for (int nt = 0; nt < 4; nt++) {
                    int p = nt >> 1, q = (nt & 1) * 2;
                    mma16816h(acc[mt][nt], a_h[mt], b_f[p][q], b_f[p][q + 1]);
                    mma16816h(acc[mt][nt], a_l[mt], b_f[p][q], b_f[p][q + 1]);
                }
        }
        __syncthreads();
    }
}

// ---------------------------------------------------------------------------
// Fused QKV projection: outputs fp16 single, Q pre-scaled.
// ---------------------------------------------------------------------------
__global__ __launch_bounds__(256) void gemm_qkv(
    const __half* __restrict__ Ah, const __half* __restrict__ Al,
    const __half* __restrict__ w16,
    const float* __restrict__ bq, const float* __restrict__ bk,
    const float* __restrict__ bv,
    __half* __restrict__ q16, __half* __restrict__ k16, __half* __restrict__ v16)
{
    extern __shared__ char smraw[];
    const uint32_t su = smem_u32(smraw);
    const int tid = threadIdx.x, lane = tid & 31, wid = tid >> 5;
    const int wsel = blockIdx.x >> 3;
    const int bn = (blockIdx.x & 7) * 128, bm = blockIdx.y * 128;
    const size_t WSZ = (size_t)D_MODEL * D_MODEL;

    const __half* Bh = w16 + (size_t)wsel * WSZ;
    const float* bias = (wsel == 0) ? bq : (wsel == 1) ? bk : bv;
    __half* C = (wsel == 0) ? q16 : (wsel == 1) ? k16 : v16;
    const float scale = (wsel == 0) ? QSCALE : 1.0f;

    float acc[4][4][4];
    #pragma unroll
    for (int i = 0; i < 4; i++)
        #pragma unroll
        for (int j = 0; j < 4; j++)
            #pragma unroll
            for (int q = 0; q < 4; q++) acc[i][j][q] = 0.0f;

    gemm_core(su, tid, bm, bn, Ah, Al, Bh, acc);

    const int wm = (wid >> 2) * 64, wn = (wid & 3) * 32;
    #pragma unroll
    for (int mt = 0; mt < 4; mt++) {
        int m0 = bm + wm + mt * 16 + (lane >> 2);
        #pragma unroll
        for (int nt = 0; nt < 4; nt++) {
            int n = bn + wn + nt * 8 + (lane & 3) * 2;
            float bx = bias[n], by = bias[n + 1];
            float v0 = (acc[mt][nt][0] + bx) * scale;
            float v1 = (acc[mt][nt][1] + by) * scale;
            float v2 = (acc[mt][nt][2] + bx) * scale;
            float v3 = (acc[mt][nt][3] + by) * scale;
            #pragma unroll
            for (int rr = 0; rr < 2; rr++) {
                int m = m0 + rr * 8;
                float a = rr ? v2 : v0, b = rr ? v3 : v1;
                int bb = m >> 11, ss = m & 2047, hh = n >> 6, dd = n & 63;
                size_t o = (((size_t)(bb * NHEADS + hh) * SEQ + ss) * HD + dd);
                *(uint32_t*)(C + o) = packh(a, b);
            }
        }
    }
}

// ---------------------------------------------------------------------------
// Output projection: fp32 flat out. A = ctx fp16 hi/lo, B = Wo fp16.
// ---------------------------------------------------------------------------
__global__ __launch_bounds__(256) void gemm_o(
    const __half* __restrict__ Ah, const __half* __restrict__ Al,
    const __half* __restrict__ Bh,
    const float* __restrict__ bias, float* __restrict__ Cf)
{
    extern __shared__ char smraw[];
    const uint32_t su = smem_u32(smraw);
    const int tid = threadIdx.x, lane = tid & 31, wid = tid >> 5;
    const int bn = blockIdx.x * 128, bm = blockIdx.y * 128;

    float acc[4][4][4];
    #pragma unroll
    for (int i = 0; i < 4; i++)
        #pragma unroll
        for (int j = 0; j < 4; j++)
            #pragma unroll
            for (int q = 0; q < 4; q++) acc[i][j][q] = 0.0f;

    gemm_core(su, tid, bm, bn, Ah, Al, Bh, acc);

    const int wm = (wid >> 2) * 64, wn = (wid & 3) * 32;
    #pragma unroll
    for (int mt = 0; mt < 4; mt++) {
        int m0 = bm + wm + mt * 16 + (lane >> 2);
        #pragma unroll
        for (int nt = 0; nt < 4; nt++) {
            int n = bn + wn + nt * 8 + (lane & 3) * 2;
            float bx = bias[n], by = bias[n + 1];
            *(float2*)(Cf + (size_t)m0 * D_MODEL + n) =
                make_float2(acc[mt][nt][0] + bx, acc[mt][nt][1] + by);
            *(float2*)(Cf + (size_t)(m0 + 8) * D_MODEL + n) =
                make_float2(acc[mt][nt][2] + bx, acc[mt][nt][3] + by);
        }
    }
}

// ---------------------------------------------------------------------------
// FA2 mma attention, plain fp16 operands (fp32 accum). BQ=128, BKV=64.
// Epilogue writes ctx as fp16 hi/lo for the exact-A O-projection.
// ---------------------------------------------------------------------------
#define ROWB 144u
#define Q_BYTES (128u * ROWB)
#define KV_ARR (64u * ROWB)
#define KV_STAGE (2u * KV_ARR)
#define SMEM_ATTN (Q_BYTES + 2u * KV_STAGE)      // 55296

__device__ __forceinline__ void attn_issue_kv(
    uint32_t sb, const __half* __restrict__ k16, const __half* __restrict__ v16,
    size_t gbase, int j0, int tid)
{
    #pragma unroll
    for (int i = 0; i < 2; i++) {
        int c = tid + i * 256;
        int r = c >> 3, u = c & 7;
        uint32_t so = (uint32_t)r * ROWB + (uint32_t)u * 16u;
        size_t go = gbase + (size_t)(j0 + r) * HD + u * 8;
        cpa16(sb + 0u * KV_ARR + so, k16 + go);
        cpa16(sb + 1u * KV_ARR + so, v16 + go);
    }
    CP_COMMIT();
}

__global__ __launch_bounds__(256) void attn_mma(
    const __half* __restrict__ q16, const __half* __restrict__ k16,
    const __half* __restrict__ v16,
    __half* __restrict__ cth, __half* __restrict__ ctl)
{
    extern __shared__ char smraw[];
    const uint32_t su = smem_u32(smraw);
    const uint32_t Q_s = su;
    const uint32_t KV0 = su + Q_BYTES;

    const int qt = (gridDim.x - 1) - blockIdx.x;
    const int h = blockIdx.y, b = blockIdx.z;
    const int bh = b * NHEADS + h;
    const size_t gbase = (size_t)bh * SEQ * HD;
    const int q0 = qt * 128;
    const int ntiles = 2 * qt + 2;

    const int tid = threadIdx.x, lane = tid & 31, wid = tid >> 5;
    const int wm = wid * 16;
    const int qr = q0 + wm;

    #pragma unroll
    for (int i = 0; i < 4; i++) {
        int c = tid + i * 256;
        int r = c >> 3, u = c & 7;
        uint32_t so = (uint32_t)r * ROWB + (uint32_t)u * 16u;
        cpa16(Q_s + so, q16 + gbase + (size_t)(q0 + r) * HD + u * 8);
    }
    attn_issue_kv(KV0, k16, v16, gbase, 0, tid);
    if (ntiles > 1) attn_issue_kv(KV0 + KV_STAGE, k16, v16, gbase, 64, tid);

    float o[8][4];
    #pragma unroll
    for (int nt = 0; nt < 8; nt++)
        #pragma unroll
        for (int q = 0; q < 4; q++) o[nt][q] = 0.0f;
    float m0 = -1e30f, m1 = -1e30f, l0 = 0.0f, l1 = 0.0f;

    for (int t = 0; t < ntiles; t++) {
        if (t + 1 < ntiles) CP_WAIT1(); else CP_WAIT0();
        __syncthreads();
        const int j0 = t * 64;
        const uint32_t sb = KV0 + (uint32_t)(t & 1) * KV_STAGE;
        const uint32_t k_s = sb, v_s = sb + KV_ARR;

        // ---- S = Q K^T (log2 domain) ----
        float s[8][4];
        #pragma unroll
        for (int nt = 0; nt < 8; nt++)
            #pragma unroll
            for (int q = 0; q < 4; q++) s[nt][q] = 0.0f;

        #pragma unroll
        for (int ks = 0; ks < 4; ks++) {
            uint32_t ah[4];
            {
                uint32_t off = (uint32_t)(wm + (lane & 15)) * ROWB
                             + (uint32_t)(ks * 16 + ((lane >> 4) << 3)) * 2u;
                LDMX4(ah, Q_s + off);
            }
            #pragma unroll
            for (int np = 0; np < 4; np++) {
                int rk = np * 16 + ((lane >> 4) << 3) + (lane & 7);
                uint32_t off = (uint32_t)rk * ROWB
                             + (uint32_t)(ks * 16 + (((lane >> 3) & 1) << 3)) * 2u;
                uint32_t kf[4];
                LDMX4(kf, k_s + off);
                #pragma unroll
                for (int q2 = 0; q2 < 2; q2++)
                    mma16816h(s[np * 2 + q2], ah, kf[q2 * 2], kf[q2 * 2 + 1]);
            }
        }

        // ---- causal mask ----
        if (j0 + 63 > qr) {
            int r0 = qr + (lane >> 2), r1 = r0 + 8;
            #pragma unroll
            for (int nt = 0; nt < 8; nt++)
                #pragma unroll
                for (int c = 0; c < 2; c++) {
                    int k = j0 + nt * 8 + (lane & 3) * 2 + c;
                    if (k > r0) s[nt][c] = -1e30f;
                    if (k > r1) s[nt][2 + c] = -1e30f;
                }
        }

        // ---- row max + rescale running state ----
        float mx0 = -1e30f, mx1 = -1e30f;
        #pragma unroll
        for (int nt = 0; nt < 8; nt++) {
            mx0 = fmaxf(mx0, fmaxf(s[nt][0], s[nt][1]));
            mx1 = fmaxf(mx1, fmaxf(s[nt][2], s[nt][3]));
        }
        mx0 = fmaxf(mx0, __shfl_xor_sync(0xffffffffu, mx0, 1));
        mx0 = fmaxf(mx0, __shfl_xor_sync(0xffffffffu, mx0, 2));
        mx1 = fmaxf(mx1, __shfl_xor_sync(0xffffffffu, mx1, 1));
        mx1 = fmaxf(mx1, __shfl_xor_sync(0xffffffffu, mx1, 2));
        float mn0 = fmaxf(m0, mx0), mn1 = fmaxf(m1, mx1);
        float c0 = ex2f(m0 - mn0), c1 = ex2f(m1 - mn1);
        m0 = mn0; m1 = mn1;
        #pragma unroll
        for (int nt = 0; nt < 8; nt++) {
            o[nt][0] *= c0; o[nt][1] *= c0;
            o[nt][2] *= c1; o[nt][3] *= c1;
        }
        float sum0 = 0.0f, sum1 = 0.0f;

        // ---- interleaved exp + P pack (fp16) + PV mma ----
        #pragma unroll
        for (int kb = 0; kb < 4; kb++) {
            uint32_t Ap[4];
            #pragma unroll
            for (int half = 0; half < 2; half++) {
                int nt = kb * 2 + half;
                float p0 = ex2f(s[nt][0] - mn0);
                float p1 = ex2f(s[nt][1] - mn0);
                float p2 = ex2f(s[nt][2] - mn1);
                float p3 = ex2f(s[nt][3] - mn1);
                sum0 += p0 + p1;
                sum1 += p2 + p3;
                Ap[half * 2 + 0] = packh(p0, p1);
                Ap[half * 2 + 1] = packh(p2, p3);
            }
            #pragma unroll
            for (int np = 0; np < 4; np++) {
                int rv = kb * 16 + (((lane >> 3) & 1) << 3) + (lane & 7);
                int cv = np * 16 + ((lane >> 4) << 3);
                uint32_t off = (uint32_t)rv * ROWB + (uint32_t)cv * 2u;
                uint32_t vf[4];
                LDMX4T(vf, v_s + off);
                #pragma unroll
                for (int q2 = 0; q2 < 2; q2++)
                    mma16816h(o[np * 2 + q2], Ap, vf[q2 * 2], vf[q2 * 2 + 1]);
            }
        }

        sum0 += __shfl_xor_sync(0xffffffffu, sum0, 1);
        sum0 += __shfl_xor_sync(0xffffffffu, sum0, 2);
        sum1 += __shfl_xor_sync(0xffffffffu, sum1, 1);
        sum1 += __shfl_xor_sync(0xffffffffu, sum1, 2);
        l0 = l0 * c0 + sum0;
        l1 = l1 * c1 + sum1;

        __syncthreads();
        if (t + 2 < ntiles)
            attn_issue_kv(KV0 + (uint32_t)(t & 1) * KV_STAGE, k16, v16,
                          gbase, (t + 2) * 64, tid);
    }

    // ---- epilogue: normalize, split fp16 hi/lo ctx ----
    float inv0 = 1.0f / l0, inv1 = 1.0f / l1;
    int r0 = qr + (lane >> 2);
    size_t tok0 = (size_t)(b * SEQ + r0) * D_MODEL + h * HD;
    size_t tok1 = tok0 + 8 * D_MODEL;
    #pragma unroll
    for (int nt = 0; nt < 8; nt++) {
        int col = nt * 8 + (lane & 3) * 2;
        float a0 = o[nt][0] * inv0, a1 = o[nt][1] * inv0;
        uint32_t uh0 = packh(a0, a1);
        float2 f0 = unpackh(uh0);
        *(uint32_t*)(cth + tok0 + col) = uh0;
        *(uint32_t*)(ctl + tok0 + col) = packh(a0 - f0.x, a1 - f0.y);
        float b0 = o[nt][2] * inv1, b1 = o[nt][3] * inv1;
        uint32_t uh1 = packh(b0, b1);
        float2 f1 = unpackh(uh1);
        *(uint32_t*)(cth + tok1 + col) = uh1;
        *(uint32_t*)(ctl + tok1 + col) = packh(b0 - f1.x, b1 - f1.y);
    }
}

// ---------------------------------------------------------------------------
extern "C" void kernel_launch(void* const* d_in, const int* in_sizes, int n_in,
                              void* d_out, int out_size)
{
    const float* x  = (const float*)d_in[0];
    const float* Wq = (const float*)d_in[1];
    const float* bq = (const float*)d_in[2];
    const float* Wk = (const float*)d_in[3];
    const float* bk = (const float*)d_in[4];
    const float* Wv = (const float*)d_in[5];
    const float* bv = (const float*)d_in[6];
    const float* Wo = (const float*)d_in[7];
    const float* bo = (const float*)d_in[8];
    float* out = (float*)d_out;

    __half *xh, *xl, *qp, *kp, *vp, *cth, *ctl, *w16;
    cudaGetSymbolAddress((void**)&xh, g_xh16);
    cudaGetSymbolAddress((void**)&xl, g_xl16);
    cudaGetSymbolAddress((void**)&qp, g_q16);
    cudaGetSymbolAddress((void**)&kp, g_k16);
    cudaGetSymbolAddress((void**)&vp, g_v16);
    cudaGetSymbolAddress((void**)&cth, g_cth16);
    cudaGetSymbolAddress((void**)&ctl, g_ctl16);
    cudaGetSymbolAddress((void**)&w16, g_w16);

    const size_t WSZ = (size_t)D_MODEL * D_MODEL;

    splith_kernel<<<1024, 256>>>(x, xh, xl, NTOK * D_MODEL);
    dim3 tg(32, 32, 4), tb(32, 8);
    tsplit4_kernel<<<tg, tb>>>(Wq, Wk, Wv, Wo, w16);

    cudaFuncSetAttribute(gemm_qkv, cudaFuncAttributeMaxDynamicSharedMemorySize, SMEM_GEMM);
    cudaFuncSetAttribute(gemm_o, cudaFuncAttributeMaxDynamicSharedMemorySize, SMEM_GEMM);

    dim3 gqkv(24, NTOK / 128);
    gemm_qkv<<<gqkv, 256, SMEM_GEMM>>>(xh, xl, w16, bq, bk, bv, qp, kp, vp);

    cudaFuncSetAttribute(attn_mma, cudaFuncAttributeMaxDynamicSharedMemorySize, SMEM_ATTN);
    dim3 ga(SEQ / 128, NHEADS, BATCH);
    attn_mma<<<ga, 256, SMEM_ATTN>>>(qp, kp, vp, cth, ctl);

    gemm_o<<<dim3(D_MODEL / 128, NTOK / 128), 256, SMEM_GEMM>>>(
        cth, ctl, w16 + 3 * WSZ, bo, out);
}

// round 11
// speedup vs baseline: 6.2979x; 1.5351x over previous
#include <cuda_runtime.h>
#include <cuda_fp16.h>
#include <cstdint>
#include <math.h>

#define D_MODEL 1024
#define NHEADS 16
#define HD 64
#define BATCH 2
#define SEQ 2048
#define NTOK (BATCH * SEQ)   // 4096

// Q pre-scale: (1/sqrt(64)) * log2(e)  -> scores in log2 domain
#define QSCALE 0.180336875967866f

// ---------------------------------------------------------------------------
// Scratch (no allocations allowed)
// ---------------------------------------------------------------------------
__device__ __half g_x16[(size_t)NTOK * D_MODEL];     // x fp16
__device__ __half g_q16[(size_t)NTOK * D_MODEL];     // [B,H,S,hd] fp16, scaled
__device__ __half g_k16[(size_t)NTOK * D_MODEL];
__device__ __half g_v16[(size_t)NTOK * D_MODEL];
__device__ __half g_ct16[(size_t)NTOK * D_MODEL];    // ctx fp16 flat [B*S][D]
__device__ __half g_w16[(size_t)4 * D_MODEL * D_MODEL];  // [n][k] transposed fp16

// ---------------------------------------------------------------------------
// Helpers (generic sm_80+ PTX only)
// ---------------------------------------------------------------------------
__device__ __forceinline__ uint32_t smem_u32(const void* p) {
    uint32_t a;
    asm("{ .reg .u64 t; cvta.to.shared.u64 t, %1; cvt.u32.u64 %0, t; }" : "=r"(a) : "l"(p));
    return a;
}
__device__ __forceinline__ void cpa16(uint32_t s, const void* g) {
    asm volatile("cp.async.cg.shared.global [%0], [%1], 16;" :: "r"(s), "l"(g));
}
#define CP_COMMIT() asm volatile("cp.async.commit_group;" ::: "memory")
#define CP_WAIT1()  asm volatile("cp.async.wait_group 1;" ::: "memory")
#define CP_WAIT0()  asm volatile("cp.async.wait_group 0;" ::: "memory")

#define LDMX4(r, a) \
    asm volatile("ldmatrix.sync.aligned.m8n8.x4.shared.b16 {%0,%1,%2,%3}, [%4];" \
        : "=r"((r)[0]), "=r"((r)[1]), "=r"((r)[2]), "=r"((r)[3]) : "r"(a))
#define LDMX4T(r, a) \
    asm volatile("ldmatrix.sync.aligned.m8n8.x4.trans.shared.b16 {%0,%1,%2,%3}, [%4];" \
        : "=r"((r)[0]), "=r"((r)[1]), "=r"((r)[2]), "=r"((r)[3]) : "r"(a))

__device__ __forceinline__ void mma16816h(float* c, const uint32_t* a, uint32_t b0, uint32_t b1) {
    asm volatile(
        "mma.sync.aligned.m16n8k16.row.col.f32.f16.f16.f32 "
        "{%0,%1,%2,%3}, {%4,%5,%6,%7}, {%8,%9}, {%0,%1,%2,%3};"
        : "+f"(c[0]), "+f"(c[1]), "+f"(c[2]), "+f"(c[3])
        : "r"(a[0]), "r"(a[1]), "r"(a[2]), "r"(a[3]), "r"(b0), "r"(b1));
}

__device__ __forceinline__ uint32_t packh(float lo, float hi) {
    uint32_t r;
    asm("cvt.rn.f16x2.f32 %0, %1, %2;" : "=r"(r) : "f"(hi), "f"(lo));
    return r;
}
__device__ __forceinline__ float ex2f(float x) {
    float y;
    asm("ex2.approx.f32 %0, %1;" : "=f"(y) : "f"(x));
    return y;
}

// ---------------------------------------------------------------------------
// Conversion kernels
// ---------------------------------------------------------------------------
__global__ void cvt16_kernel(const float* __restrict__ s, __half* __restrict__ d, int n) {
    int i = blockIdx.x * blockDim.x + threadIdx.x;
    int stride = gridDim.x * blockDim.x;
    for (int j = i * 2; j < n; j += stride * 2) {
        float2 v = *(const float2*)(s + j);
        *(uint32_t*)(d + j) = packh(v.x, v.y);
    }
}

// Fused: 4 weights [k][n] fp32 -> single fp16 [n][k]; blockIdx.z selects weight
__global__ void tsplit4_kernel(const float* __restrict__ W0, const float* __restrict__ W1,
                               const float* __restrict__ W2, const float* __restrict__ W3,
                               __half* __restrict__ t16) {
    __shared__ float t[32][33];
    const int z = blockIdx.z;
    const float* W = (z == 0) ? W0 : (z == 1) ? W1 : (z == 2) ? W2 : W3;
    const size_t WSZ = (size_t)D_MODEL * D_MODEL;
    __half* tz = t16 + z * WSZ;
    int n0 = blockIdx.x * 32, k0 = blockIdx.y * 32;
    int x = threadIdx.x, y = threadIdx.y;  // 32x8
    #pragma unroll
    for (int j = 0; j < 32; j += 8)
        t[y + j][x] = W[(size_t)(k0 + y + j) * D_MODEL + n0 + x];
    __syncthreads();
    #pragma unroll
    for (int j = 0; j < 32; j += 8)
        tz[(size_t)(n0 + y + j) * D_MODEL + k0 + x] = __float2half(t[x][y + j]);
}

// ---------------------------------------------------------------------------
// Shared GEMM mainloop: single-fp16 A, single-fp16 B, fp32 accum
// ---------------------------------------------------------------------------
#define ABYTES 10240u
#define STAGEB (2u * ABYTES)       // A, B
#define SMEM_GEMM (2u * STAGEB)    // 40960

__device__ __forceinline__ void issue_stage(
    uint32_t su, int stage, int k0, int tid, int bm, int bn,
    const __half* __restrict__ A, const __half* __restrict__ B)
{
    uint32_t sb = su + (uint32_t)stage * STAGEB;
    #pragma unroll
    for (int j = 0; j < 2; j++) {
        int idx = tid + j * 256;
        int r = idx >> 2, c8 = idx & 3;
        uint32_t so = (uint32_t)(r * 40 + c8 * 8) * 2;
        cpa16(sb + 0u * ABYTES + so, A + (size_t)(bm + r) * D_MODEL + k0 + c8 * 8);
        cpa16(sb + 1u * ABYTES + so, B + (size_t)(bn + r) * D_MODEL + k0 + c8 * 8);
    }
    CP_COMMIT();
}

__device__ __forceinline__ void gemm_core(
    uint32_t su, int tid, int bm, int bn,
    const __half* __restrict__ A, const __half* __restrict__ B,
    float acc[4][4][4])
{
    const int lane = tid & 31, wid = tid >> 5;
    const int wm = (wid >> 2) * 64, wn = (wid & 3) * 32;

    issue_stage(su, 0, 0, tid, bm, bn, A, B);

    const int NKT = D_MODEL / 32;
    for (int kt = 0; kt < NKT; kt++) {
        if (kt + 1 < NKT) {
            issue_stage(su, (kt + 1) & 1, (kt + 1) * 32, tid, bm, bn, A, B);
            CP_WAIT1();
        } else {
            CP_WAIT0();
        }
        __syncthreads();
        uint32_t sb = su + (uint32_t)(kt & 1) * STAGEB;

        #pragma unroll
        for (int ks = 0; ks < 32; ks += 16) {
            uint32_t a_f[4][4], b_f[2][4];
            #pragma unroll
            for (int mt = 0; mt < 4; mt++) {
                uint32_t off = (uint32_t)((wm + mt * 16 + (lane & 15)) * 40
                                          + ks + ((lane >> 4) << 3)) * 2;
                LDMX4(a_f[mt], sb + 0u * ABYTES + off);
            }
            #pragma unroll
            for (int p = 0; p < 2; p++) {
                int rb = wn + p * 16 + (lane & 7) + ((lane >> 4) << 3);
                int ce = ks + (((lane >> 3) & 1) << 3);
                uint32_t off = (uint32_t)(rb * 40 + ce) * 2;
                LDMX4(b_f[p], sb + 1u * ABYTES + off);
            }
            #pragma unroll
            for (int mt = 0; mt < 4; mt++)
                #pragma unroll
                for (int nt = 0; nt < 4; nt++) {
                    int p = nt >> 1, q = (nt & 1) * 2;
                    mma16816h(acc[mt][nt], a_f[mt], b_f[p][q], b_f[p][q + 1]);
                }
        }
        __syncthreads();
    }
}

// ---------------------------------------------------------------------------
// Fused QKV projection: outputs fp16, Q pre-scaled.
// ---------------------------------------------------------------------------
__global__ __launch_bounds__(256) void gemm_qkv(
    const __half* __restrict__ x16, const __half* __restrict__ w16,
    const float* __restrict__ bq, const float* __restrict__ bk,
    const float* __restrict__ bv,
    __half* __restrict__ q16, __half* __restrict__ k16, __half* __restrict__ v16)
{
    extern __shared__ char smraw[];
    const uint32_t su = smem_u32(smraw);
    const int tid = threadIdx.x, lane = tid & 31, wid = tid >> 5;
    const int wsel = blockIdx.x >> 3;
    const int bn = (blockIdx.x & 7) * 128, bm = blockIdx.y * 128;
    const size_t WSZ = (size_t)D_MODEL * D_MODEL;

    const __half* B = w16 + (size_t)wsel * WSZ;
    const float* bias = (wsel == 0) ? bq : (wsel == 1) ? bk : bv;
    __half* C = (wsel == 0) ? q16 : (wsel == 1) ? k16 : v16;
    const float scale = (wsel == 0) ? QSCALE : 1.0f;

    float acc[4][4][4];
    #pragma unroll
    for (int i = 0; i < 4; i++)
        #pragma unroll
        for (int j = 0; j < 4; j++)
            #pragma unroll
            for (int q = 0; q < 4; q++) acc[i][j][q] = 0.0f;

    gemm_core(su, tid, bm, bn, x16, B, acc);

    const int wm = (wid >> 2) * 64, wn = (wid & 3) * 32;
    #pragma unroll
    for (int mt = 0; mt < 4; mt++) {
        int m0 = bm + wm + mt * 16 + (lane >> 2);
        #pragma unroll
        for (int nt = 0; nt < 4; nt++) {
            int n = bn + wn + nt * 8 + (lane & 3) * 2;
            float bx = bias[n], by = bias[n + 1];
            float v0 = (acc[mt][nt][0] + bx) * scale;
            float v1 = (acc[mt][nt][1] + by) * scale;
            float v2 = (acc[mt][nt][2] + bx) * scale;
            float v3 = (acc[mt][nt][3] + by) * scale;
            #pragma unroll
            for (int rr = 0; rr < 2; rr++) {
                int m = m0 + rr * 8;
                float a = rr ? v2 : v0, b = rr ? v3 : v1;
                int bb = m >> 11, ss = m & 2047, hh = n >> 6, dd = n & 63;
                size_t o = (((size_t)(bb * NHEADS + hh) * SEQ + ss) * HD + dd);
                *(uint32_t*)(C + o) = packh(a, b);
            }
        }
    }
}

// ---------------------------------------------------------------------------
// Output projection: fp32 flat out. A = ctx fp16, B = Wo fp16.
// ---------------------------------------------------------------------------
__global__ __launch_bounds__(256) void gemm_o(
    const __half* __restrict__ ct16, const __half* __restrict__ Bw,
    const float* __restrict__ bias, float* __restrict__ Cf)
{
    extern __shared__ char smraw[];
    const uint32_t su = smem_u32(smraw);
    const int tid = threadIdx.x, lane = tid & 31, wid = tid >> 5;
    const int bn = blockIdx.x * 128, bm = blockIdx.y * 128;

    float acc[4][4][4];
    #pragma unroll
    for (int i = 0; i < 4; i++)
        #pragma unroll
        for (int j = 0; j < 4; j++)
            #pragma unroll
            for (int q = 0; q < 4; q++) acc[i][j][q] = 0.0f;

    gemm_core(su, tid, bm, bn, ct16, Bw, acc);

    const int wm = (wid >> 2) * 64, wn = (wid & 3) * 32;
    #pragma unroll
    for (int mt = 0; mt < 4; mt++) {
        int m0 = bm + wm + mt * 16 + (lane >> 2);
        #pragma unroll
        for (int nt = 0; nt < 4; nt++) {
            int n = bn + wn + nt * 8 + (lane & 3) * 2;
            float bx = bias[n], by = bias[n + 1];
            *(float2*)(Cf + (size_t)m0 * D_MODEL + n) =
                make_float2(acc[mt][nt][0] + bx, acc[mt][nt][1] + by);
            *(float2*)(Cf + (size_t)(m0 + 8) * D_MODEL + n) =
                make_float2(acc[mt][nt][2] + bx, acc[mt][nt][3] + by);
        }
    }
}

// ---------------------------------------------------------------------------
// FA2 mma attention, plain fp16 operands (fp32 accum). BQ=128, BKV=64.
// ---------------------------------------------------------------------------
#define ROWB 144u
#define Q_BYTES (128u * ROWB)
#define KV_ARR (64u * ROWB)
#define KV_STAGE (2u * KV_ARR)
#define SMEM_ATTN (Q_BYTES + 2u * KV_STAGE)      // 55296

__device__ __forceinline__ void attn_issue_kv(
    uint32_t sb, const __half* __restrict__ k16, const __half* __restrict__ v16,
    size_t gbase, int j0, int tid)
{
    #pragma unroll
    for (int i = 0; i < 2; i++) {
        int c = tid + i * 256;
        int r = c >> 3, u = c & 7;
        uint32_t so = (uint32_t)r * ROWB + (uint32_t)u * 16u;
        size_t go = gbase + (size_t)(j0 + r) * HD + u * 8;
        cpa16(sb + 0u * KV_ARR + so, k16 + go);
        cpa16(sb + 1u * KV_ARR + so, v16 + go);
    }
    CP_COMMIT();
}

__global__ __launch_bounds__(256) void attn_mma(
    const __half* __restrict__ q16, const __half* __restrict__ k16,
    const __half* __restrict__ v16, __half* __restrict__ ct16)
{
    extern __shared__ char smraw[];
    const uint32_t su = smem_u32(smraw);
    const uint32_t Q_s = su;
    const uint32_t KV0 = su + Q_BYTES;

    const int qt = (gridDim.x - 1) - blockIdx.x;
    const int h = blockIdx.y, b = blockIdx.z;
    const int bh = b * NHEADS + h;
    const size_t gbase = (size_t)bh * SEQ * HD;
    const int q0 = qt * 128;
    const int ntiles = 2 * qt + 2;

    const int tid = threadIdx.x, lane = tid & 31, wid = tid >> 5;
    const int wm = wid * 16;
    const int qr = q0 + wm;

    #pragma unroll
    for (int i = 0; i < 4; i++) {
        int c = tid + i * 256;
        int r = c >> 3, u = c & 7;
        uint32_t so = (uint32_t)r * ROWB + (uint32_t)u * 16u;
        cpa16(Q_s + so, q16 + gbase + (size_t)(q0 + r) * HD + u * 8);
    }
    attn_issue_kv(KV0, k16, v16, gbase, 0, tid);
    if (ntiles > 1) attn_issue_kv(KV0 + KV_STAGE, k16, v16, gbase, 64, tid);

    float o[8][4];
    #pragma unroll
    for (int nt = 0; nt < 8; nt++)
        #pragma unroll
        for (int q = 0; q < 4; q++) o[nt][q] = 0.0f;
    float m0 = -1e30f, m1 = -1e30f, l0 = 0.0f, l1 = 0.0f;

    for (int t = 0; t < ntiles; t++) {
        if (t + 1 < ntiles) CP_WAIT1(); else CP_WAIT0();
        __syncthreads();
        const int j0 = t * 64;
        const uint32_t sb = KV0 + (uint32_t)(t & 1) * KV_STAGE;
        const uint32_t k_s = sb, v_s = sb + KV_ARR;

        // ---- S = Q K^T (log2 domain) ----
        float s[8][4];
        #pragma unroll
        for (int nt = 0; nt < 8; nt++)
            #pragma unroll
            for (int q = 0; q < 4; q++) s[nt][q] = 0.0f;

        #pragma unroll
        for (int ks = 0; ks < 4; ks++) {
            uint32_t ah[4];
            {
                uint32_t off = (uint32_t)(wm + (lane & 15)) * ROWB
                             + (uint32_t)(ks * 16 + ((lane >> 4) << 3)) * 2u;
                LDMX4(ah, Q_s + off);
            }
            #pragma unroll
            for (int np = 0; np < 4; np++) {
                int rk = np * 16 + ((lane >> 4) << 3) + (lane & 7);
                uint32_t off = (uint32_t)rk * ROWB
                             + (uint32_t)(ks * 16 + (((lane >> 3) & 1) << 3)) * 2u;
                uint32_t kf[4];
                LDMX4(kf, k_s + off);
                #pragma unroll
                for (int q2 = 0; q2 < 2; q2++)
                    mma16816h(s[np * 2 + q2], ah, kf[q2 * 2], kf[q2 * 2 + 1]);
            }
        }

        // ---- causal mask ----
        if (j0 + 63 > qr) {
            int r0 = qr + (lane >> 2), r1 = r0 + 8;
            #pragma unroll
            for (int nt = 0; nt < 8; nt++)
                #pragma unroll
                for (int c = 0; c < 2; c++) {
                    int k = j0 + nt * 8 + (lane & 3) * 2 + c;
                    if (k > r0) s[nt][c] = -1e30f;
                    if (k > r1) s[nt][2 + c] = -1e30f;
                }
        }

        // ---- row max + rescale running state ----
        float mx0 = -1e30f, mx1 = -1e30f;
        #pragma unroll
        for (int nt = 0; nt < 8; nt++) {
            mx0 = fmaxf(mx0, fmaxf(s[nt][0], s[nt][1]));
            mx1 = fmaxf(mx1, fmaxf(s[nt][2], s[nt][3]));
        }
        mx0 = fmaxf(mx0, __shfl_xor_sync(0xffffffffu, mx0, 1));
        mx0 = fmaxf(mx0, __shfl_xor_sync(0xffffffffu, mx0, 2));
        mx1 = fmaxf(mx1, __shfl_xor_sync(0xffffffffu, mx1, 1));
        mx1 = fmaxf(mx1, __shfl_xor_sync(0xffffffffu, mx1, 2));
        float mn0 = fmaxf(m0, mx0), mn1 = fmaxf(m1, mx1);
        float c0 = ex2f(m0 - mn0), c1 = ex2f(m1 - mn1);
        m0 = mn0; m1 = mn1;
        #pragma unroll
        for (int nt = 0; nt < 8; nt++) {
            o[nt][0] *= c0; o[nt][1] *= c0;
            o[nt][2] *= c1; o[nt][3] *= c1;
        }
        float sum0 = 0.0f, sum1 = 0.0f;

        // ---- interleaved exp + P pack (fp16) + PV mma ----
        #pragma unroll
        for (int kb = 0; kb < 4; kb++) {
            uint32_t Ap[4];
            #pragma unroll
            for (int half = 0; half < 2; half++) {
                int nt = kb * 2 + half;
                float p0 = ex2f(s[nt][0] - mn0);
                float p1 = ex2f(s[nt][1] - mn0);
                float p2 = ex2f(s[nt][2] - mn1);
                float p3 = ex2f(s[nt][3] - mn1);
                sum0 += p0 + p1;
                sum1 += p2 + p3;
                Ap[half * 2 + 0] = packh(p0, p1);
                Ap[half * 2 + 1] = packh(p2, p3);
            }
            #pragma unroll
            for (int np = 0; np < 4; np++) {
                int rv = kb * 16 + (((lane >> 3) & 1) << 3) + (lane & 7);
                int cv = np * 16 + ((lane >> 4) << 3);
                uint32_t off = (uint32_t)rv * ROWB + (uint32_t)cv * 2u;
                uint32_t vf[4];
                LDMX4T(vf, v_s + off);
                #pragma unroll
                for (int q2 = 0; q2 < 2; q2++)
                    mma16816h(o[np * 2 + q2], Ap, vf[q2 * 2], vf[q2 * 2 + 1]);
            }
        }

        sum0 += __shfl_xor_sync(0xffffffffu, sum0, 1);
        sum0 += __shfl_xor_sync(0xffffffffu, sum0, 2);
        sum1 += __shfl_xor_sync(0xffffffffu, sum1, 1);
        sum1 += __shfl_xor_sync(0xffffffffu, sum1, 2);
        l0 = l0 * c0 + sum0;
        l1 = l1 * c1 + sum1;

        __syncthreads();
        if (t + 2 < ntiles)
            attn_issue_kv(KV0 + (uint32_t)(t & 1) * KV_STAGE, k16, v16,
                          gbase, (t + 2) * 64, tid);
    }

    // ---- epilogue: normalize, write fp16 ctx ----
    float inv0 = 1.0f / l0, inv1 = 1.0f / l1;
    int r0 = qr + (lane >> 2);
    size_t tok0 = (size_t)(b * SEQ + r0) * D_MODEL + h * HD;
    size_t tok1 = tok0 + 8 * D_MODEL;
    #pragma unroll
    for (int nt = 0; nt < 8; nt++) {
        int col = nt * 8 + (lane & 3) * 2;
        *(uint32_t*)(ct16 + tok0 + col) = packh(o[nt][0] * inv0, o[nt][1] * inv0);
        *(uint32_t*)(ct16 + tok1 + col) = packh(o[nt][2] * inv1, o[nt][3] * inv1);
    }
}

// ---------------------------------------------------------------------------
extern "C" void kernel_launch(void* const* d_in, const int* in_sizes, int n_in,
                              void* d_out, int out_size)
{
    const float* x  = (const float*)d_in[0];
    const float* Wq = (const float*)d_in[1];
    const float* bq = (const float*)d_in[2];
    const float* Wk = (const float*)d_in[3];
    const float* bk = (const float*)d_in[4];
    const float* Wv = (const float*)d_in[5];
    const float* bv = (const float*)d_in[6];
    const float* Wo = (const float*)d_in[7];
    const float* bo = (const float*)d_in[8];
    float* out = (float*)d_out;

    __half *x16, *qp, *kp, *vp, *ct16, *w16;
    cudaGetSymbolAddress((void**)&x16, g_x16);
    cudaGetSymbolAddress((void**)&qp, g_q16);
    cudaGetSymbolAddress((void**)&kp, g_k16);
    cudaGetSymbolAddress((void**)&vp, g_v16);
    cudaGetSymbolAddress((void**)&ct16, g_ct16);
    cudaGetSymbolAddress((void**)&w16, g_w16);

    const size_t WSZ = (size_t)D_MODEL * D_MODEL;

    cvt16_kernel<<<1024, 256>>>(x, x16, NTOK * D_MODEL);
    dim3 tg(32, 32, 4), tb(32, 8);
    tsplit4_kernel<<<tg, tb>>>(Wq, Wk, Wv, Wo, w16);

    cudaFuncSetAttribute(gemm_qkv, cudaFuncAttributeMaxDynamicSharedMemorySize, SMEM_GEMM);
    cudaFuncSetAttribute(gemm_o, cudaFuncAttributeMaxDynamicSharedMemorySize, SMEM_GEMM);

    dim3 gqkv(24, NTOK / 128);
    gemm_qkv<<<gqkv, 256, SMEM_GEMM>>>(x16, w16, bq, bk, bv, qp, kp, vp);

    cudaFuncSetAttribute(attn_mma, cudaFuncAttributeMaxDynamicSharedMemorySize, SMEM_ATTN);
    dim3 ga(SEQ / 128, NHEADS, BATCH);
    attn_mma<<<ga, 256, SMEM_ATTN>>>(qp, kp, vp, ct16);

    gemm_o<<<dim3(D_MODEL / 128, NTOK / 128), 256, SMEM_GEMM>>>(
        ct16, w16 + 3 * WSZ, bo, out);
}

// round 13
// speedup vs baseline: 6.8204x; 1.0830x over previous
#include <cuda_runtime.h>
#include <cuda_fp16.h>
#include <cstdint>
#include <math.h>

#define D_MODEL 1024
#define NHEADS 16
#define HD 64
#define BATCH 2
#define SEQ 2048
#define NTOK (BATCH * SEQ)   // 4096

// Q pre-scale: (1/sqrt(64)) * log2(e)  -> scores in log2 domain
#define QSCALE 0.180336875967866f

// ---------------------------------------------------------------------------
// Scratch (no allocations allowed)
// ---------------------------------------------------------------------------
__device__ __half g_x16[(size_t)NTOK * D_MODEL];
__device__ __half g_q16[(size_t)NTOK * D_MODEL];   // [B,H,S,hd] fp16, scaled
__device__ __half g_k16[(size_t)NTOK * D_MODEL];
__device__ __half g_v16[(size_t)NTOK * D_MODEL];
__device__ __half g_ct16[(size_t)NTOK * D_MODEL];  // ctx fp16 flat
__device__ __half g_w16[(size_t)4 * D_MODEL * D_MODEL];  // [n][k] fp16

// ---------------------------------------------------------------------------
// Helpers
// ---------------------------------------------------------------------------
__device__ __forceinline__ uint32_t smem_u32(const void* p) {
    uint32_t a;
    asm("{ .reg .u64 t; cvta.to.shared.u64 t, %1; cvt.u32.u64 %0, t; }" : "=r"(a) : "l"(p));
    return a;
}
__device__ __forceinline__ void cpa16(uint32_t s, const void* g) {
    asm volatile("cp.async.cg.shared.global [%0], [%1], 16;" :: "r"(s), "l"(g));
}
#define CP_COMMIT() asm volatile("cp.async.commit_group;" ::: "memory")
#define CP_WAIT2()  asm volatile("cp.async.wait_group 2;" ::: "memory")
#define CP_WAIT1()  asm volatile("cp.async.wait_group 1;" ::: "memory")
#define CP_WAIT0()  asm volatile("cp.async.wait_group 0;" ::: "memory")

#define LDMX4(r, a) \
    asm volatile("ldmatrix.sync.aligned.m8n8.x4.shared.b16 {%0,%1,%2,%3}, [%4];" \
        : "=r"((r)[0]), "=r"((r)[1]), "=r"((r)[2]), "=r"((r)[3]) : "r"(a))
#define LDMX4T(r, a) \
    asm volatile("ldmatrix.sync.aligned.m8n8.x4.trans.shared.b16 {%0,%1,%2,%3}, [%4];" \
        : "=r"((r)[0]), "=r"((r)[1]), "=r"((r)[2]), "=r"((r)[3]) : "r"(a))

__device__ __forceinline__ void mma16816h(float* c, const uint32_t* a, uint32_t b0, uint32_t b1) {
    asm volatile(
        "mma.sync.aligned.m16n8k16.row.col.f32.f16.f16.f32 "
        "{%0,%1,%2,%3}, {%4,%5,%6,%7}, {%8,%9}, {%0,%1,%2,%3};"
        : "+f"(c[0]), "+f"(c[1]), "+f"(c[2]), "+f"(c[3])
        : "r"(a[0]), "r"(a[1]), "r"(a[2]), "r"(a[3]), "r"(b0), "r"(b1));
}

__device__ __forceinline__ uint32_t packh(float lo, float hi) {
    uint32_t r;
    asm("cvt.rn.f16x2.f32 %0, %1, %2;" : "=r"(r) : "f"(hi), "f"(lo));
    return r;
}
__device__ __forceinline__ float ex2f(float x) {
    float y;
    asm("ex2.approx.f32 %0, %1;" : "=f"(y) : "f"(x));
    return y;
}

// ---------------------------------------------------------------------------
// Conversion kernels
// ---------------------------------------------------------------------------
__global__ void cvt16_kernel(const float* __restrict__ s, __half* __restrict__ d, int n) {
    int i = blockIdx.x * blockDim.x + threadIdx.x;
    int stride = gridDim.x * blockDim.x;
    for (int j = i * 2; j < n; j += stride * 2) {
        float2 v = *(const float2*)(s + j);
        *(uint32_t*)(d + j) = packh(v.x, v.y);
    }
}

__global__ void tsplit4_kernel(const float* __restrict__ W0, const float* __restrict__ W1,
                               const float* __restrict__ W2, const float* __restrict__ W3,
                               __half* __restrict__ t16) {
    __shared__ float t[32][33];
    const int z = blockIdx.z;
    const float* W = (z == 0) ? W0 : (z == 1) ? W1 : (z == 2) ? W2 : W3;
    const size_t WSZ = (size_t)D_MODEL * D_MODEL;
    __half* tz = t16 + z * WSZ;
    int n0 = blockIdx.x * 32, k0 = blockIdx.y * 32;
    int x = threadIdx.x, y = threadIdx.y;
    #pragma unroll
    for (int j = 0; j < 32; j += 8)
        t[y + j][x] = W[(size_t)(k0 + y + j) * D_MODEL + n0 + x];
    __syncthreads();
    #pragma unroll
    for (int j = 0; j < 32; j += 8)
        tz[(size_t)(n0 + y + j) * D_MODEL + k0 + x] = __float2half(t[x][y + j]);
}

// ---------------------------------------------------------------------------
// GEMM mainloop: fp16 A/B, fp32 accum, BK=64 per stage (halved barrier count)
// rows padded to 72 elems (144 B) -> conflict-free ldmatrix
// ---------------------------------------------------------------------------
#define GROWE 72u
#define GABYTES (128u * GROWE * 2u)   // 18432 per array tile (128 x 64 fp16)
#define GSTAGEB (2u * GABYTES)        // A + B = 36864
#define SMEM_GEMM (2u * GSTAGEB)      // 73728

__device__ __forceinline__ void issue_stage(
    uint32_t su, int stage, int k0, int tid, int bm, int bn,
    const __half* __restrict__ A, const __half* __restrict__ B)
{
    uint32_t sb = su + (uint32_t)stage * GSTAGEB;
    #pragma unroll
    for (int j = 0; j < 4; j++) {
        int idx = tid + j * 256;           // 0..1023
        int r = idx >> 3, cu = idx & 7;    // r 0..127, cu 0..7 (16B units)
        uint32_t so = (uint32_t)r * (GROWE * 2u) + (uint32_t)cu * 16u;
        cpa16(sb + 0u * GABYTES + so, A + (size_t)(bm + r) * D_MODEL + k0 + cu * 8);
        cpa16(sb + 1u * GABYTES + so, B + (size_t)(bn + r) * D_MODEL + k0 + cu * 8);
    }
    CP_COMMIT();
}

__device__ __forceinline__ void gemm_core(
    uint32_t su, int tid, int bm, int bn,
    const __half* __restrict__ A, const __half* __restrict__ B,
    float acc[4][4][4])
{
    const int lane = tid & 31, wid = tid >> 5;
    const int wm = (wid >> 2) * 64, wn = (wid & 3) * 32;

    issue_stage(su, 0, 0, tid, bm, bn, A, B);

    const int NKT = D_MODEL / 64;   // 16
    for (int kt = 0; kt < NKT; kt++) {
        if (kt + 1 < NKT) {
            issue_stage(su, (kt + 1) & 1, (kt + 1) * 64, tid, bm, bn, A, B);
            CP_WAIT1();
        } else {
            CP_WAIT0();
        }
        __syncthreads();
        uint32_t sb = su + (uint32_t)(kt & 1) * GSTAGEB;

        #pragma unroll
        for (int ks = 0; ks < 64; ks += 16) {
            uint32_t a_f[4][4], b_f[2][4];
            #pragma unroll
            for (int mt = 0; mt < 4; mt++) {
                uint32_t off = (uint32_t)((wm + mt * 16 + (lane & 15)) * GROWE
                                          + ks + ((lane >> 4) << 3)) * 2;
                LDMX4(a_f[mt], sb + 0u * GABYTES + off);
            }
            #pragma unroll
            for (int p = 0; p < 2; p++) {
                int rb = wn + p * 16 + (lane & 7) + ((lane >> 4) << 3);
                int ce = ks + (((lane >> 3) & 1) << 3);
                uint32_t off = (uint32_t)(rb * GROWE + ce) * 2;
                LDMX4(b_f[p], sb + 1u * GABYTES + off);
            }
            #pragma unroll
            for (int mt = 0; mt < 4; mt++)
                #pragma unroll
                for (int nt = 0; nt < 4; nt++) {
                    int p = nt >> 1, q = (nt & 1) * 2;
                    mma16816h(acc[mt][nt], a_f[mt], b_f[p][q], b_f[p][q + 1]);
                }
        }
        __syncthreads();
    }
}

// ---------------------------------------------------------------------------
// Fused QKV projection: outputs fp16, Q pre-scaled.
// ---------------------------------------------------------------------------
__global__ __launch_bounds__(256) void gemm_qkv(
    const __half* __restrict__ x16, const __half* __restrict__ w16,
    const float* __restrict__ bq, const float* __restrict__ bk,
    const float* __restrict__ bv,
    __half* __restrict__ q16, __half* __restrict__ k16, __half* __restrict__ v16)
{
    extern __shared__ char smraw[];
    const uint32_t su = smem_u32(smraw);
    const int tid = threadIdx.x, lane = tid & 31, wid = tid >> 5;
    const int wsel = blockIdx.x >> 3;
    const int bn = (blockIdx.x & 7) * 128, bm = blockIdx.y * 128;
    const size_t WSZ = (size_t)D_MODEL * D_MODEL;

    const __half* B = w16 + (size_t)wsel * WSZ;
    const float* bias = (wsel == 0) ? bq : (wsel == 1) ? bk : bv;
    __half* C = (wsel == 0) ? q16 : (wsel == 1) ? k16 : v16;
    const float scale = (wsel == 0) ? QSCALE : 1.0f;

    float acc[4][4][4];
    #pragma unroll
    for (int i = 0; i < 4; i++)
        #pragma unroll
        for (int j = 0; j < 4; j++)
            #pragma unroll
            for (int q = 0; q < 4; q++) acc[i][j][q] = 0.0f;

    gemm_core(su, tid, bm, bn, x16, B, acc);

    const int wm = (wid >> 2) * 64, wn = (wid & 3) * 32;
    #pragma unroll
    for (int mt = 0; mt < 4; mt++) {
        int m0 = bm + wm + mt * 16 + (lane >> 2);
        #pragma unroll
        for (int nt = 0; nt < 4; nt++) {
            int n = bn + wn + nt * 8 + (lane & 3) * 2;
            float bx = bias[n], by = bias[n + 1];
            float v0 = (acc[mt][nt][0] + bx) * scale;
            float v1 = (acc[mt][nt][1] + by) * scale;
            float v2 = (acc[mt][nt][2] + bx) * scale;
            float v3 = (acc[mt][nt][3] + by) * scale;
            #pragma unroll
            for (int rr = 0; rr < 2; rr++) {
                int m = m0 + rr * 8;
                float a = rr ? v2 : v0, b = rr ? v3 : v1;
                int bb = m >> 11, ss = m & 2047, hh = n >> 6, dd = n & 63;
                size_t o = (((size_t)(bb * NHEADS + hh) * SEQ + ss) * HD + dd);
                *(uint32_t*)(C + o) = packh(a, b);
            }
        }
    }
}

// ---------------------------------------------------------------------------
// Output projection: fp32 flat out
// ---------------------------------------------------------------------------
__global__ __launch_bounds__(256) void gemm_o(
    const __half* __restrict__ ct16, const __half* __restrict__ Bw,
    const float* __restrict__ bias, float* __restrict__ Cf)
{
    extern __shared__ char smraw[];
    const uint32_t su = smem_u32(smraw);
    const int tid = threadIdx.x, lane = tid & 31, wid = tid >> 5;
    const int bn = blockIdx.x * 128, bm = blockIdx.y * 128;

    float acc[4][4][4];
    #pragma unroll
    for (int i = 0; i < 4; i++)
        #pragma unroll
        for (int j = 0; j < 4; j++)
            #pragma unroll
            for (int q = 0; q < 4; q++) acc[i][j][q] = 0.0f;

    gemm_core(su, tid, bm, bn, ct16, Bw, acc);

    const int wm = (wid >> 2) * 64, wn = (wid & 3) * 32;
    #pragma unroll
    for (int mt = 0; mt < 4; mt++) {
        int m0 = bm + wm + mt * 16 + (lane >> 2);
        #pragma unroll
        for (int nt = 0; nt < 4; nt++) {
            int n = bn + wn + nt * 8 + (lane & 3) * 2;
            float bx = bias[n], by = bias[n + 1];
            *(float2*)(Cf + (size_t)m0 * D_MODEL + n) =
                make_float2(acc[mt][nt][0] + bx, acc[mt][nt][1] + by);
            *(float2*)(Cf + (size_t)(m0 + 8) * D_MODEL + n) =
                make_float2(acc[mt][nt][2] + bx, acc[mt][nt][3] + by);
        }
    }
}

// ---------------------------------------------------------------------------
// FA2 mma attention, fp16 operands, 3-stage KV cp.async pipeline.
// ---------------------------------------------------------------------------
#define ROWB 144u
#define Q_BYTES (128u * ROWB)
#define KV_ARR (64u * ROWB)
#define KV_STAGE (2u * KV_ARR)                   // K, V
#define SMEM_ATTN (Q_BYTES + 3u * KV_STAGE)      // 73728

__device__ __forceinline__ void attn_issue_kv(
    uint32_t sb, const __half* __restrict__ k16, const __half* __restrict__ v16,
    size_t gbase, int j0, int tid)
{
    #pragma unroll
    for (int i = 0; i < 2; i++) {
        int c = tid + i * 256;
        int r = c >> 3, u = c & 7;
        uint32_t so = (uint32_t)r * ROWB + (uint32_t)u * 16u;
        size_t go = gbase + (size_t)(j0 + r) * HD + u * 8;
        cpa16(sb + 0u * KV_ARR + so, k16 + go);
        cpa16(sb + 1u * KV_ARR + so, v16 + go);
    }
    CP_COMMIT();
}

__global__ __launch_bounds__(256) void attn_mma(
    const __half* __restrict__ q16, const __half* __restrict__ k16,
    const __half* __restrict__ v16, __half* __restrict__ ct16)
{
    extern __shared__ char smraw[];
    const uint32_t su = smem_u32(smraw);
    const uint32_t Q_s = su;
    const uint32_t KV0 = su + Q_BYTES;

    const int qt = (gridDim.x - 1) - blockIdx.x;
    const int h = blockIdx.y, b = blockIdx.z;
    const int bh = b * NHEADS + h;
    const size_t gbase = (size_t)bh * SEQ * HD;
    const int q0 = qt * 128;
    const int ntiles = 2 * qt + 2;

    const int tid = threadIdx.x, lane = tid & 31, wid = tid >> 5;
    const int wm = wid * 16;
    const int qr = q0 + wm;

    // Q load joins commit group 0
    #pragma unroll
    for (int i = 0; i < 4; i++) {
        int c = tid + i * 256;
        int r = c >> 3, u = c & 7;
        uint32_t so = (uint32_t)r * ROWB + (uint32_t)u * 16u;
        cpa16(Q_s + so, q16 + gbase + (size_t)(q0 + r) * HD + u * 8);
    }
    attn_issue_kv(KV0, k16, v16, gbase, 0, tid);
    if (ntiles > 1) attn_issue_kv(KV0 + KV_STAGE, k16, v16, gbase, 64, tid);
    if (ntiles > 2) attn_issue_kv(KV0 + 2u * KV_STAGE, k16, v16, gbase, 128, tid);

    float o[8][4];
    #pragma unroll
    for (int nt = 0; nt < 8; nt++)
        #pragma unroll
        for (int q = 0; q < 4; q++) o[nt][q] = 0.0f;
    float m0 = -1e30f, m1 = -1e30f, l0 = 0.0f, l1 = 0.0f;

    int slot = 0;
    for (int t = 0; t < ntiles; t++) {
        // committed at this point = min(ntiles, 3 + max(0, t)) limited by issue rule;
        // needed pending: 2 while steady-state, 1 at t==ntiles-2, 0 at last
        if (t <= ntiles - 3)      CP_WAIT2();
        else if (t == ntiles - 2) CP_WAIT1();
        else                      CP_WAIT0();
        __syncthreads();
        const int j0 = t * 64;
        const uint32_t sb = KV0 + (uint32_t)slot * KV_STAGE;
        const uint32_t k_s = sb, v_s = sb + KV_ARR;

        // ---- S = Q K^T (log2 domain) ----
        float s[8][4];
        #pragma unroll
        for (int nt = 0; nt < 8; nt++)
            #pragma unroll
            for (int q = 0; q < 4; q++) s[nt][q] = 0.0f;

        #pragma unroll
        for (int ks = 0; ks < 4; ks++) {
            uint32_t ah[4];
            {
                uint32_t off = (uint32_t)(wm + (lane & 15)) * ROWB
                             + (uint32_t)(ks * 16 + ((lane >> 4) << 3)) * 2u;
                LDMX4(ah, Q_s + off);
            }
            #pragma unroll
            for (int np = 0; np < 4; np++) {
                int rk = np * 16 + ((lane >> 4) << 3) + (lane & 7);
                uint32_t off = (uint32_t)rk * ROWB
                             + (uint32_t)(ks * 16 + (((lane >> 3) & 1) << 3)) * 2u;
                uint32_t kf[4];
                LDMX4(kf, k_s + off);
                #pragma unroll
                for (int q2 = 0; q2 < 2; q2++)
                    mma16816h(s[np * 2 + q2], ah, kf[q2 * 2], kf[q2 * 2 + 1]);
            }
        }

        // ---- causal mask ----
        if (j0 + 63 > qr) {
            int r0 = qr + (lane >> 2), r1 = r0 + 8;
            #pragma unroll
            for (int nt = 0; nt < 8; nt++)
                #pragma unroll
                for (int c = 0; c < 2; c++) {
                    int k = j0 + nt * 8 + (lane & 3) * 2 + c;
                    if (k > r0) s[nt][c] = -1e30f;
                    if (k > r1) s[nt][2 + c] = -1e30f;
                }
        }

        // ---- row max + rescale ----
        float mx0 = -1e30f, mx1 = -1e30f;
        #pragma unroll
        for (int nt = 0; nt < 8; nt++) {
            mx0 = fmaxf(mx0, fmaxf(s[nt][0], s[nt][1]));
            mx1 = fmaxf(mx1, fmaxf(s[nt][2], s[nt][3]));
        }
        mx0 = fmaxf(mx0, __shfl_xor_sync(0xffffffffu, mx0, 1));
        mx0 = fmaxf(mx0, __shfl_xor_sync(0xffffffffu, mx0, 2));
        mx1 = fmaxf(mx1, __shfl_xor_sync(0xffffffffu, mx1, 1));
        mx1 = fmaxf(mx1, __shfl_xor_sync(0xffffffffu, mx1, 2));
        float mn0 = fmaxf(m0, mx0), mn1 = fmaxf(m1, mx1);
        float c0 = ex2f(m0 - mn0), c1 = ex2f(m1 - mn1);
        m0 = mn0; m1 = mn1;
        #pragma unroll
        for (int nt = 0; nt < 8; nt++) {
            o[nt][0] *= c0; o[nt][1] *= c0;
            o[nt][2] *= c1; o[nt][3] *= c1;
        }
        float sum0 = 0.0f, sum1 = 0.0f;

        // ---- interleaved exp + P pack + PV mma ----
        #pragma unroll
        for (int kb = 0; kb < 4; kb++) {
            uint32_t Ap[4];
            #pragma unroll
            for (int half = 0; half < 2; half++) {
                int nt = kb * 2 + half;
                float p0 = ex2f(s[nt][0] - mn0);
                float p1 = ex2f(s[nt][1] - mn0);
                float p2 = ex2f(s[nt][2] - mn1);
                float p3 = ex2f(s[nt][3] - mn1);
                sum0 += p0 + p1;
                sum1 += p2 + p3;
                Ap[half * 2 + 0] = packh(p0, p1);
                Ap[half * 2 + 1] = packh(p2, p3);
            }
            #pragma unroll
            for (int np = 0; np < 4; np++) {
                int rv = kb * 16 + (((lane >> 3) & 1) << 3) + (lane & 7);
                int cv = np * 16 + ((lane >> 4) << 3);
                uint32_t off = (uint32_t)rv * ROWB + (uint32_t)cv * 2u;
                uint32_t vf[4];
                LDMX4T(vf, v_s + off);
                #pragma unroll
                for (int q2 = 0; q2 < 2; q2++)
                    mma16816h(o[np * 2 + q2], Ap, vf[q2 * 2], vf[q2 * 2 + 1]);
            }
        }

        sum0 += __shfl_xor_sync(0xffffffffu, sum0, 1);
        sum0 += __shfl_xor_sync(0xffffffffu, sum0, 2);
        sum1 += __shfl_xor_sync(0xffffffffu, sum1, 1);
        sum1 += __shfl_xor_sync(0xffffffffu, sum1, 2);
        l0 = l0 * c0 + sum0;
        l1 = l1 * c1 + sum1;

        __syncthreads();
        if (t + 3 < ntiles)
            attn_issue_kv(KV0 + (uint32_t)slot * KV_STAGE, k16, v16,
                          gbase, (t + 3) * 64, tid);
        slot = (slot == 2) ? 0 : slot + 1;
    }

    // ---- epilogue ----
    float inv0 = 1.0f / l0, inv1 = 1.0f / l1;
    int r0 = qr + (lane >> 2);
    size_t tok0 = (size_t)(b * SEQ + r0) * D_MODEL + h * HD;
    size_t tok1 = tok0 + 8 * D_MODEL;
    #pragma unroll
    for (int nt = 0; nt < 8; nt++) {
        int col = nt * 8 + (lane & 3) * 2;
        *(uint32_t*)(ct16 + tok0 + col) = packh(o[nt][0] * inv0, o[nt][1] * inv0);
        *(uint32_t*)(ct16 + tok1 + col) = packh(o[nt][2] * inv1, o[nt][3] * inv1);
    }
}

// ---------------------------------------------------------------------------
extern "C" void kernel_launch(void* const* d_in, const int* in_sizes, int n_in,
                              void* d_out, int out_size)
{
    const float* x  = (const float*)d_in[0];
    const float* Wq = (const float*)d_in[1];
    const float* bq = (const float*)d_in[2];
    const float* Wk = (const float*)d_in[3];
    const float* bk = (const float*)d_in[4];
    const float* Wv = (const float*)d_in[5];
    const float* bv = (const float*)d_in[6];
    const float* Wo = (const float*)d_in[7];
    const float* bo = (const float*)d_in[8];
    float* out = (float*)d_out;

    __half *x16, *qp, *kp, *vp, *ct16, *w16;
    cudaGetSymbolAddress((void**)&x16, g_x16);
    cudaGetSymbolAddress((void**)&qp, g_q16);
    cudaGetSymbolAddress((void**)&kp, g_k16);
    cudaGetSymbolAddress((void**)&vp, g_v16);
    cudaGetSymbolAddress((void**)&ct16, g_ct16);
    cudaGetSymbolAddress((void**)&w16, g_w16);

    const size_t WSZ = (size_t)D_MODEL * D_MODEL;

    cvt16_kernel<<<1024, 256>>>(x, x16, NTOK * D_MODEL);
    dim3 tg(32, 32, 4), tb(32, 8);
    tsplit4_kernel<<<tg, tb>>>(Wq, Wk, Wv, Wo, w16);

    cudaFuncSetAttribute(gemm_qkv, cudaFuncAttributeMaxDynamicSharedMemorySize, SMEM_GEMM);
    cudaFuncSetAttribute(gemm_o, cudaFuncAttributeMaxDynamicSharedMemorySize, SMEM_GEMM);

    dim3 gqkv(24, NTOK / 128);
    gemm_qkv<<<gqkv, 256, SMEM_GEMM>>>(x16, w16, bq, bk, bv, qp, kp, vp);

    cudaFuncSetAttribute(attn_mma, cudaFuncAttributeMaxDynamicSharedMemorySize, SMEM_ATTN);
    dim3 ga(SEQ / 128, NHEADS, BATCH);
    attn_mma<<<ga, 256, SMEM_ATTN>>>(qp, kp, vp, ct16);

    gemm_o<<<dim3(D_MODEL / 128, NTOK / 128), 256, SMEM_GEMM>>>(
        ct16, w16 + 3 * WSZ, bo, out);
}